// round 12
// baseline (speedup 1.0000x reference)
#include <cuda_runtime.h>
#include <cuda_bf16.h>
#include <cuda_fp16.h>
#include <cstdint>

#define E_EDGES 1600000
#define N_NODES 50000
#define EPS_BN 1e-5f

// ---------------- scratch (device globals; no allocations allowed) ----------
__device__ __half g_Y[(size_t)E_EDGES * 128];     // pre-BN edge activations (fp16)
__device__ float g_P[(size_t)N_NODES * 128];      // x @ W1_top + b1
__device__ float g_s[(size_t)N_NODES * 128];      // scatter-sum accumulator
__device__ int   g_cnt[N_NODES];
__device__ float g_h2in[(size_t)N_NODES * 256];
__device__ float g_Z2[(size_t)N_NODES * 256];
__device__ float g_sum1[128], g_ssq1[128], g_scale1[128], g_shift1[128];
__device__ float g_sum2[256], g_ssq2[256], g_scale2[256], g_shift2[256];
// Weight images (padded rows, uint4-clean)
__device__ uint4 g_W1bH16[1088];                   // W1_bot fp16 [64 k][136 n]
__device__ uint4 g_W1tH[2176],    g_W1tL[2176];    // W1_top bf16 [128 k][136 n]
__device__ uint4 g_W2H[8448],     g_W2L[8448];     // W2    bf16 [256 k][264 n]
__device__ uint4 g_WlH[4352],     g_WlL[4352];     // Wl    bf16 [256 k][136 n]

__device__ __forceinline__ float4 ld4(const float* p) {
    return *reinterpret_cast<const float4*>(p);
}
__device__ __forceinline__ uint32_t smem_u32(const void* p) {
    uint32_t a;
    asm("{ .reg .u64 t; cvta.to.shared.u64 t, %1; cvt.u32.u64 %0, t; }" : "=r"(a) : "l"(p));
    return a;
}

// ---------------- warp MMA primitives (sm_80 baseline) ----------------------
__device__ __forceinline__ void mma_bf16(float* c, const uint32_t* a, const uint32_t* b) {
    asm volatile(
        "mma.sync.aligned.m16n8k16.row.col.f32.bf16.bf16.f32 "
        "{%0,%1,%2,%3}, {%4,%5,%6,%7}, {%8,%9}, {%0,%1,%2,%3};"
        : "+f"(c[0]), "+f"(c[1]), "+f"(c[2]), "+f"(c[3])
        : "r"(a[0]), "r"(a[1]), "r"(a[2]), "r"(a[3]), "r"(b[0]), "r"(b[1]));
}
__device__ __forceinline__ void mma_f16(float* c, const uint32_t* a, const uint32_t* b) {
    asm volatile(
        "mma.sync.aligned.m16n8k16.row.col.f32.f16.f16.f32 "
        "{%0,%1,%2,%3}, {%4,%5,%6,%7}, {%8,%9}, {%0,%1,%2,%3};"
        : "+f"(c[0]), "+f"(c[1]), "+f"(c[2]), "+f"(c[3])
        : "r"(a[0]), "r"(a[1]), "r"(a[2]), "r"(a[3]), "r"(b[0]), "r"(b[1]));
}
__device__ __forceinline__ void ldsm4(uint32_t* r, uint32_t addr) {
    asm volatile("ldmatrix.sync.aligned.m8n8.x4.shared.b16 {%0,%1,%2,%3}, [%4];"
        : "=r"(r[0]), "=r"(r[1]), "=r"(r[2]), "=r"(r[3]) : "r"(addr));
}
__device__ __forceinline__ void ldsm4t(uint32_t* r, uint32_t addr) {
    asm volatile("ldmatrix.sync.aligned.m8n8.x4.trans.shared.b16 {%0,%1,%2,%3}, [%4];"
        : "=r"(r[0]), "=r"(r[1]), "=r"(r[2]), "=r"(r[3]) : "r"(addr));
}
__device__ __forceinline__ void split_store(char* hi, char* lo, int j, float4 v) {
    __nv_bfloat16 h0 = __float2bfloat16_rn(v.x), h1 = __float2bfloat16_rn(v.y);
    __nv_bfloat16 h2 = __float2bfloat16_rn(v.z), h3 = __float2bfloat16_rn(v.w);
    __nv_bfloat162 hp0(h0, h1), hp1(h2, h3);
    __nv_bfloat162 lp0(__float2bfloat16_rn(v.x - __bfloat162float(h0)),
                       __float2bfloat16_rn(v.y - __bfloat162float(h1)));
    __nv_bfloat162 lp1(__float2bfloat16_rn(v.z - __bfloat162float(h2)),
                       __float2bfloat16_rn(v.w - __bfloat162float(h3)));
    *reinterpret_cast<uint2*>(hi + j * 8) =
        make_uint2(*reinterpret_cast<uint32_t*>(&hp0), *reinterpret_cast<uint32_t*>(&hp1));
    *reinterpret_cast<uint2*>(lo + j * 8) =
        make_uint2(*reinterpret_cast<uint32_t*>(&lp0), *reinterpret_cast<uint32_t*>(&lp1));
}
__device__ __forceinline__ void cp_async16(uint32_t saddr, const void* gptr) {
    asm volatile("cp.async.cg.shared.global [%0], [%1], 16;"
                 :: "r"(saddr), "l"(gptr) : "memory");
}
__device__ __forceinline__ void prefetchL1(const void* gptr) {
    asm volatile("prefetch.global.L1 [%0];" :: "l"(gptr));
}

// ---------------- zero scratch ----------------------------------------------
__global__ void zero_kernel() {
    int idx = blockIdx.x * blockDim.x + threadIdx.x;
    int stride = gridDim.x * blockDim.x;
    float4 z4 = make_float4(0.f, 0.f, 0.f, 0.f);
    int total4 = N_NODES * 32;
    float4* s4 = reinterpret_cast<float4*>(g_s);
    for (int i = idx; i < total4; i += stride) s4[i] = z4;
    for (int i = idx; i < N_NODES; i += stride) g_cnt[i] = 0;
    if (idx < 128) { g_sum1[idx] = 0.f; g_ssq1[idx] = 0.f; }
    if (idx < 256) { g_sum2[idx] = 0.f; g_ssq2[idx] = 0.f; }
}

// ---------------- prep: all weight images ------------------------------------
__global__ void prep_W(const float* __restrict__ W1, const float* __restrict__ W2,
                       const float* __restrict__ Wl) {
    int idx = blockIdx.x * blockDim.x + threadIdx.x;
    if (idx < 8192) {                       // W1_bot fp16: [64 k][128 n] -> 136
        int k = idx >> 7, n = idx & 127;
        float f = W1[(size_t)(128 + k) * 128 + n];
        __half h = __float2half_rn(f);
        reinterpret_cast<uint16_t*>(g_W1bH16)[k * 136 + n] = *reinterpret_cast<uint16_t*>(&h);
        return;
    }
    float f;
    uint16_t *dh, *dl;
    int off;
    if (idx < 24576) {                      // W1_top bf16: [128 k][128 n] -> 136
        int l = idx - 8192, k = l >> 7, n = l & 127;
        f = W1[(size_t)k * 128 + n];
        dh = reinterpret_cast<uint16_t*>(g_W1tH);
        dl = reinterpret_cast<uint16_t*>(g_W1tL);
        off = k * 136 + n;
    } else if (idx < 90112) {               // W2 bf16: [256 k][256 n] -> 264
        int l = idx - 24576, k = l >> 8, n = l & 255;
        f = W2[(size_t)k * 256 + n];
        dh = reinterpret_cast<uint16_t*>(g_W2H);
        dl = reinterpret_cast<uint16_t*>(g_W2L);
        off = k * 264 + n;
    } else if (idx < 122880) {              // Wl bf16: [256 k][128 n] -> 136
        int l = idx - 90112, k = l >> 7, n = l & 127;
        f = Wl[(size_t)k * 128 + n];
        dh = reinterpret_cast<uint16_t*>(g_WlH);
        dl = reinterpret_cast<uint16_t*>(g_WlL);
        off = k * 136 + n;
    } else return;
    __nv_bfloat16 h = __float2bfloat16_rn(f);
    __nv_bfloat16 l = __float2bfloat16_rn(f - __bfloat162float(h));
    dh[off] = *reinterpret_cast<uint16_t*>(&h);
    dl[off] = *reinterpret_cast<uint16_t*>(&l);
}

// ---------------- SMEM layouts ------------------------------------------------
// mma_gemm (bf16 3-pass, unchanged):
#define Q_AHI 0
#define Q_ALO 18432
#define Q_WHI 36864
#define Q_WLO 54272
#define Q_ROW 71680
#define Q_SUM 72192
#define Q_SSQ 72704
#define Q_TOT 73216
#define A_STRIDE 144
// gemm1 (fp16 single-pass, persistent, 3 CTAs/SM):
#define G3_A 0
#define G3_W 18432
#define G3_STAGE 35840       // raw eattr tile [128][272B] = 34816
#define G3_SROWSTG 70656
#define G3_SROW 71168
#define G3_SUM 71680
#define G3_SSQ 72192
#define G3_TOT 72704
#define G_GRID 444           // 3 CTAs/SM x 148 SMs
#define G_NT (E_EDGES / 128)

// ---------------- gemm1 (persistent, fp16 1-pass): Y = eattr@W1_bot + P[row] --
__global__ void __launch_bounds__(256, 3)
gemm1_mma(const float* __restrict__ eattr, const int* __restrict__ erow) {
    extern __shared__ char smem[];
    const uint32_t sb = smem_u32(smem);
    const int tid = threadIdx.x, wid = tid >> 5, lane = tid & 31;

    // one-time: W fp16 image, stat init
    {
        uint4* dw = reinterpret_cast<uint4*>(smem + G3_W);
        for (int i = tid; i < 1088; i += 256) dw[i] = g_W1bH16[i];
    }
    if (tid < 128) {
        ((float*)(smem + G3_SUM))[tid] = 0.f;
        ((float*)(smem + G3_SSQ))[tid] = 0.f;
    }

    // prologue: stage first tile
    {
        int t0 = blockIdx.x;
        if (t0 < G_NT) {
            const char* src = (const char*)(eattr + (size_t)t0 * 128 * 64);
            #pragma unroll
            for (int i = tid; i < 2048; i += 256) {
                int r = i >> 4, q = i & 15;
                cp_async16(sb + G3_STAGE + r * 272 + q * 16, src + (size_t)r * 256 + q * 16);
            }
            if (tid < 32)
                cp_async16(sb + G3_SROWSTG + tid * 16,
                           (const char*)(erow + (size_t)t0 * 128) + tid * 16);
        }
        asm volatile("cp.async.commit_group;" ::: "memory");
    }

    const int m0 = (wid & 3) * 32;
    const int n0 = (wid >> 2) * 64;
    const uint32_t aRowOff = (uint32_t)(m0 + (lane & 15)) * (uint32_t)A_STRIDE
                           + (uint32_t)(lane >> 4) * 16u;
    const uint32_t bOff = (uint32_t)((lane & 7) + ((lane >> 3) & 1) * 8) * 272u
                        + ((uint32_t)(lane >> 4) * 8u + (uint32_t)n0) * 2u;
    const int g = lane >> 2, t2 = (lane & 3) * 2;
    const int* s_row = (const int*)(smem + G3_SROW);
    float* s_sum = (float*)(smem + G3_SUM);
    float* s_ssq = (float*)(smem + G3_SSQ);

    float csum[8][2], cssq[8][2];
    #pragma unroll
    for (int ni = 0; ni < 8; ++ni) {
        csum[ni][0] = 0.f; csum[ni][1] = 0.f;
        cssq[ni][0] = 0.f; cssq[ni][1] = 0.f;
    }

    for (int t = blockIdx.x; t < G_NT; t += G_GRID) {
        asm volatile("cp.async.wait_group 0;" ::: "memory");
        __syncthreads();   // stage ready; prior MMA/epilogue done

        // convert stage -> single fp16 A image; publish erow
        {
            const int r = tid >> 1, h = tid & 1;
            const char* srow = smem + G3_STAGE + r * 272;
            char* ai = smem + G3_A + r * A_STRIDE;
            #pragma unroll
            for (int p = 0; p < 4; ++p) {
                int j = h * 8 + p * 2;
                float4 v0 = *reinterpret_cast<const float4*>(srow + j * 16);
                float4 v1 = *reinterpret_cast<const float4*>(srow + j * 16 + 16);
                __half2 a = __floats2half2_rn(v0.x, v0.y);
                __half2 b = __floats2half2_rn(v0.z, v0.w);
                __half2 c = __floats2half2_rn(v1.x, v1.y);
                __half2 d = __floats2half2_rn(v1.z, v1.w);
                uint4 pk = make_uint4(*reinterpret_cast<uint32_t*>(&a),
                                      *reinterpret_cast<uint32_t*>(&b),
                                      *reinterpret_cast<uint32_t*>(&c),
                                      *reinterpret_cast<uint32_t*>(&d));
                *reinterpret_cast<uint4*>(ai + j * 8) = pk;
            }
            if (tid < 128)
                ((int*)(smem + G3_SROW))[tid] = ((const int*)(smem + G3_SROWSTG))[tid];
        }
        __syncthreads();   // image + s_row visible; stage consumed

        // gather rows + P prefetch (hidden by MMA)
        int G00 = s_row[m0 + g],      G01 = s_row[m0 + g + 8];
        int G10 = s_row[m0 + 16 + g], G11 = s_row[m0 + 16 + g + 8];
        {
            const float* pb = g_P;
            prefetchL1(pb + (size_t)G00 * 128 + n0 + t2);
            prefetchL1(pb + (size_t)G00 * 128 + n0 + t2 + 32);
            prefetchL1(pb + (size_t)G01 * 128 + n0 + t2);
            prefetchL1(pb + (size_t)G01 * 128 + n0 + t2 + 32);
            prefetchL1(pb + (size_t)G10 * 128 + n0 + t2);
            prefetchL1(pb + (size_t)G10 * 128 + n0 + t2 + 32);
            prefetchL1(pb + (size_t)G11 * 128 + n0 + t2);
            prefetchL1(pb + (size_t)G11 * 128 + n0 + t2 + 32);
        }

        // stage next tile
        if (t + G_GRID < G_NT) {
            int tn = t + G_GRID;
            const char* src = (const char*)(eattr + (size_t)tn * 128 * 64);
            #pragma unroll
            for (int i = tid; i < 2048; i += 256) {
                int r = i >> 4, q = i & 15;
                cp_async16(sb + G3_STAGE + r * 272 + q * 16, src + (size_t)r * 256 + q * 16);
            }
            if (tid < 32)
                cp_async16(sb + G3_SROWSTG + tid * 16,
                           (const char*)(erow + (size_t)tn * 128) + tid * 16);
        }
        asm volatile("cp.async.commit_group;" ::: "memory");

        // ---- MMA: single fp16 pass ----
        float acc[2][8][4];
        #pragma unroll
        for (int mi = 0; mi < 2; ++mi)
            #pragma unroll
            for (int ni = 0; ni < 8; ++ni)
                #pragma unroll
                for (int c = 0; c < 4; ++c) acc[mi][ni][c] = 0.f;

        #pragma unroll
        for (int kt = 0; kt < 4; ++kt) {
            const uint32_t k0b = (uint32_t)kt * 32u;
            const uint32_t kwb = (uint32_t)kt * 4352u;
            uint32_t a0[4], a1[4];
            ldsm4(a0, sb + G3_A + aRowOff + k0b);
            ldsm4(a1, sb + G3_A + aRowOff + 16u * A_STRIDE + k0b);

            #pragma unroll
            for (int ni2 = 0; ni2 < 4; ++ni2) {
                uint32_t th[4];
                ldsm4t(th, sb + G3_W + bOff + kwb + (uint32_t)ni2 * 32u);
                mma_f16(acc[0][2 * ni2],     a0, th);
                mma_f16(acc[0][2 * ni2 + 1], a0, th + 2);
                mma_f16(acc[1][2 * ni2],     a1, th);
                mma_f16(acc[1][2 * ni2 + 1], a1, th + 2);
            }
        }

        // ---- epilogue: Y = Q + P[row] (L1-hot), fp16 streaming store --------
        const int mBase = t * 128;
        #pragma unroll
        for (int mi = 0; mi < 2; ++mi) {
            const int r0 = m0 + mi * 16 + g;
            const int G0 = (mi == 0) ? G00 : G10;
            const int G1 = (mi == 0) ? G01 : G11;
            const int row = mBase + r0;
            #pragma unroll
            for (int ni = 0; ni < 8; ++ni) {
                const int col = n0 + ni * 8 + t2;
                float2 p0 = *reinterpret_cast<const float2*>(g_P + (size_t)G0 * 128 + col);
                float2 p1 = *reinterpret_cast<const float2*>(g_P + (size_t)G1 * 128 + col);
                float y0 = acc[mi][ni][0] + p0.x;
                float y1 = acc[mi][ni][1] + p0.y;
                float y2 = acc[mi][ni][2] + p1.x;
                float y3 = acc[mi][ni][3] + p1.y;
                __half2 h01 = __floats2half2_rn(y0, y1);
                __half2 h23 = __floats2half2_rn(y2, y3);
                __stcs(reinterpret_cast<__half2*>(g_Y + (size_t)row * 128 + col), h01);
                __stcs(reinterpret_cast<__half2*>(g_Y + (size_t)(row + 8) * 128 + col), h23);
                csum[ni][0] += y0 + y2;
                csum[ni][1] += y1 + y3;
                cssq[ni][0] += y0 * y0 + y2 * y2;
                cssq[ni][1] += y1 * y1 + y3 * y3;
            }
        }
    }

    // ---- one-time BN1 stats reduction + global flush ----
    #pragma unroll
    for (int ni = 0; ni < 8; ++ni)
        #pragma unroll
        for (int par = 0; par < 2; ++par) {
            float s = csum[ni][par], q = cssq[ni][par];
            #pragma unroll
            for (int o = 4; o < 32; o <<= 1) {
                s += __shfl_xor_sync(0xFFFFFFFFu, s, o);
                q += __shfl_xor_sync(0xFFFFFFFFu, q, o);
            }
            if (g == 0) {
                atomicAdd(&s_sum[n0 + ni * 8 + t2 + par], s);
                atomicAdd(&s_ssq[n0 + ni * 8 + t2 + par], q);
            }
        }
    __syncthreads();
    if (tid < 128) {
        atomicAdd(&g_sum1[tid], s_sum[tid]);
        atomicAdd(&g_ssq1[tid], s_ssq[tid]);
    }
}

// ---------------- unified k-chunked bf16-split MMA GEMM (unchanged) ----------
// ASEL: 0=ext arg (x), 1=g_h2in, 2=g_Z2 (+bn2+relu transform)
// WSEL: 0=W1_top(17), 1=W2(33), 2=Wl(17)
// OSEL: 0=g_P, 1=g_Z2(+BN2 stats), 2=ext out arg(+relu)
template<int KCH, int ASEL, int WSEL, int OSEL>
__global__ void __launch_bounds__(256, 2)
mma_gemm(const float* __restrict__ Aext, int ldA, int M,
         const float* __restrict__ bias, float* __restrict__ outExt, int outLd)
{
    extern __shared__ char smem[];
    const uint32_t sb = smem_u32(smem);
    const int tid = threadIdx.x, wid = tid >> 5, lane = tid & 31;
    const int mBase = blockIdx.x * 128;
    const int nBase = blockIdx.y * 128;

    const float* A = (ASEL == 0) ? Aext : (ASEL == 1) ? (const float*)g_h2in
                                                      : (const float*)g_Z2;
    const uint4* WH = (WSEL == 0) ? g_W1tH : (WSEL == 1) ? g_W2H : g_WlH;
    const uint4* WL = (WSEL == 0) ? g_W1tL : (WSEL == 1) ? g_W2L : g_WlL;
    const int WR16 = (WSEL == 1) ? 33 : 17;
    float* outp = (OSEL == 0) ? (float*)g_P : (OSEL == 1) ? (float*)g_Z2 : outExt;

    if (tid < 128) {
        ((float*)(smem + Q_ROW))[tid] = bias[nBase + tid];
        ((float*)(smem + Q_SUM))[tid] = 0.f;
        ((float*)(smem + Q_SSQ))[tid] = 0.f;
    }

    const int m0 = (wid & 3) * 32;
    const int n0 = (wid >> 2) * 64;
    float acc[2][8][4];
    #pragma unroll
    for (int mi = 0; mi < 2; ++mi)
        #pragma unroll
        for (int ni = 0; ni < 8; ++ni)
            #pragma unroll
            for (int c = 0; c < 4; ++c) acc[mi][ni][c] = 0.f;

    const uint32_t aRowOff = (uint32_t)(m0 + (lane & 15)) * (uint32_t)A_STRIDE
                           + (uint32_t)(lane >> 4) * 16u;
    const uint32_t bOff = (uint32_t)((lane & 7) + ((lane >> 3) & 1) * 8) * 272u
                        + ((uint32_t)(lane >> 4) * 8u + (uint32_t)n0) * 2u;

    #pragma unroll 1
    for (int c = 0; c < KCH; ++c) {
        if (c) __syncthreads();
        {
            uint4* dh = reinterpret_cast<uint4*>(smem + Q_WHI);
            uint4* dl = reinterpret_cast<uint4*>(smem + Q_WLO);
            const uint4* sh = WH + (size_t)(c * 64) * WR16 + (nBase >> 3);
            const uint4* sl = WL + (size_t)(c * 64) * WR16 + (nBase >> 3);
            for (int i = tid; i < 1088; i += 256) {
                int kk = i / 17, q = i - kk * 17;
                dh[i] = sh[(size_t)kk * WR16 + q];
                dl[i] = sl[(size_t)kk * WR16 + q];
            }
        }
        {
            const int r = tid >> 1, h = tid & 1, rg = mBase + r;
            char* ahi = smem + Q_AHI + r * A_STRIDE;
            char* alo = smem + Q_ALO + r * A_STRIDE;
            const float4* ar = reinterpret_cast<const float4*>(A + (size_t)rg * ldA + c * 64);
            #pragma unroll
            for (int jj = 0; jj < 8; ++jj) {
                int j = h * 8 + jj;
                float4 v = make_float4(0.f, 0.f, 0.f, 0.f);
                if (rg < M) {
                    v = ar[j];
                    if (ASEL == 2) {
                        int kg = c * 64 + j * 4;
                        float4 sc = ld4(g_scale2 + kg), sh4 = ld4(g_shift2 + kg);
                        v.x = fmaxf(fmaf(v.x, sc.x, sh4.x), 0.f);
                        v.y = fmaxf(fmaf(v.y, sc.y, sh4.y), 0.f);
                        v.z = fmaxf(fmaf(v.z, sc.z, sh4.z), 0.f);
                        v.w = fmaxf(fmaf(v.w, sc.w, sh4.w), 0.f);
                    }
                }
                split_store(ahi, alo, j, v);
            }
        }
        __syncthreads();

        #pragma unroll
        for (int kt = 0; kt < 4; ++kt) {
            const uint32_t k0b = (uint32_t)kt * 32u;
            const uint32_t kwb = (uint32_t)kt * 4352u;
            uint32_t ah[2][4], al[2][4];
            ldsm4(ah[0], sb + Q_AHI + aRowOff + k0b);
            ldsm4(ah[1], sb + Q_AHI + aRowOff + 16u * A_STRIDE + k0b);
            ldsm4(al[0], sb + Q_ALO + aRowOff + k0b);
            ldsm4(al[1], sb + Q_ALO + aRowOff + 16u * A_STRIDE + k0b);

            #pragma unroll
            for (int ni2 = 0; ni2 < 4; ++ni2) {
                uint32_t th[4], tl[4];
                ldsm4t(th, sb + Q_WHI + bOff + kwb + (uint32_t)ni2 * 32u);
                ldsm4t(tl, sb + Q_WLO + bOff + kwb + (uint32_t)ni2 * 32u);
                #pragma unroll
                for (int mi = 0; mi < 2; ++mi) {
                    mma_bf16(acc[mi][2 * ni2],     ah[mi], th);
                    mma_bf16(acc[mi][2 * ni2],     al[mi], th);
                    mma_bf16(acc[mi][2 * ni2],     ah[mi], tl);
                    mma_bf16(acc[mi][2 * ni2 + 1], ah[mi], th + 2);
                    mma_bf16(acc[mi][2 * ni2 + 1], al[mi], th + 2);
                    mma_bf16(acc[mi][2 * ni2 + 1], ah[mi], tl + 2);
                }
            }
        }
    }
    __syncthreads();

    const float* bs = (const float*)(smem + Q_ROW);
    float* s_sum = (float*)(smem + Q_SUM);
    float* s_ssq = (float*)(smem + Q_SSQ);
    const int g = lane >> 2, t2 = (lane & 3) * 2;

    float csum[8][2], cssq[8][2];
    if (OSEL == 1) {
        #pragma unroll
        for (int ni = 0; ni < 8; ++ni) {
            csum[ni][0] = 0.f; csum[ni][1] = 0.f;
            cssq[ni][0] = 0.f; cssq[ni][1] = 0.f;
        }
    }

    #pragma unroll
    for (int mi = 0; mi < 2; ++mi) {
        const int row = mBase + m0 + mi * 16 + g;
        const bool v0 = row < M, v1 = (row + 8) < M;
        #pragma unroll
        for (int ni = 0; ni < 8; ++ni) {
            const int col = n0 + ni * 8 + t2;
            float b0 = bs[col], b1 = bs[col + 1];
            float y0 = acc[mi][ni][0] + b0;
            float y1 = acc[mi][ni][1] + b1;
            float y2 = acc[mi][ni][2] + b0;
            float y3 = acc[mi][ni][3] + b1;
            if (OSEL == 2) {
                y0 = fmaxf(y0, 0.f); y1 = fmaxf(y1, 0.f);
                y2 = fmaxf(y2, 0.f); y3 = fmaxf(y3, 0.f);
            }
            if (v0)
                *reinterpret_cast<float2*>(outp + (size_t)row * outLd + nBase + col)
                    = make_float2(y0, y1);
            if (v1)
                *reinterpret_cast<float2*>(outp + (size_t)(row + 8) * outLd + nBase + col)
                    = make_float2(y2, y3);
            if (OSEL == 1) {
                if (v0) {
                    csum[ni][0] += y0; csum[ni][1] += y1;
                    cssq[ni][0] += y0 * y0; cssq[ni][1] += y1 * y1;
                }
                if (v1) {
                    csum[ni][0] += y2; csum[ni][1] += y3;
                    cssq[ni][0] += y2 * y2; cssq[ni][1] += y3 * y3;
                }
            }
        }
    }
    if (OSEL == 1) {
        #pragma unroll
        for (int ni = 0; ni < 8; ++ni)
            #pragma unroll
            for (int par = 0; par < 2; ++par) {
                float s = csum[ni][par], q = cssq[ni][par];
                #pragma unroll
                for (int o = 4; o < 32; o <<= 1) {
                    s += __shfl_xor_sync(0xFFFFFFFFu, s, o);
                    q += __shfl_xor_sync(0xFFFFFFFFu, q, o);
                }
                if (g == 0) {
                    atomicAdd(&s_sum[n0 + ni * 8 + t2 + par], s);
                    atomicAdd(&s_ssq[n0 + ni * 8 + t2 + par], q);
                }
            }
        __syncthreads();
        if (tid < 128) {
            atomicAdd(&g_sum2[nBase + tid], s_sum[tid]);
            atomicAdd(&g_ssq2[nBase + tid], s_ssq[tid]);
        }
    }
}

// ---------------- BN finalize -------------------------------------------------
__global__ void finalize_bn(const float* __restrict__ gamma,
                            const float* __restrict__ beta,
                            int C, float invM, int which)
{
    int i = blockIdx.x * blockDim.x + threadIdx.x;
    if (i < C) {
        const float* sum = (which == 0) ? g_sum1 : g_sum2;
        const float* ssq = (which == 0) ? g_ssq1 : g_ssq2;
        float*     scale = (which == 0) ? g_scale1 : g_scale2;
        float*     shift = (which == 0) ? g_shift1 : g_shift2;
        float mu  = sum[i] * invM;
        float var = ssq[i] * invM - mu * mu;
        float inv = rsqrtf(var + EPS_BN);
        float sc  = gamma[i] * inv;
        scale[i] = sc;
        shift[i] = beta[i] - mu * sc;
    }
}

// ---------------- BN+ReLU then scatter-add (fp16 Y, vector atomics) ----------
__global__ void scatter_kernel(const int* __restrict__ ecol) {
    const int lane   = threadIdx.x & 31;
    const int warp   = (blockIdx.x * blockDim.x + threadIdx.x) >> 5;
    const int nWarps = (gridDim.x * blockDim.x) >> 5;

    float4 sc = *reinterpret_cast<const float4*>(&g_scale1[lane << 2]);
    float4 sh = *reinterpret_cast<const float4*>(&g_shift1[lane << 2]);

    for (int e = warp; e < E_EDGES; e += nWarps) {
        int c = ecol[e];
        uint2 raw = __ldcs(reinterpret_cast<const uint2*>(&g_Y[(size_t)e * 128 + (lane << 2)]));
        __half2 ha = *reinterpret_cast<__half2*>(&raw.x);
        __half2 hb = *reinterpret_cast<__half2*>(&raw.y);
        float2 f01 = __half22float2(ha);
        float2 f23 = __half22float2(hb);
        float y0 = fmaxf(fmaf(f01.x, sc.x, sh.x), 0.f);
        float y1 = fmaxf(fmaf(f01.y, sc.y, sh.y), 0.f);
        float y2 = fmaxf(fmaf(f23.x, sc.z, sh.z), 0.f);
        float y3 = fmaxf(fmaf(f23.y, sc.w, sh.w), 0.f);
        float* dst = &g_s[(size_t)c * 128 + (lane << 2)];
        asm volatile("red.global.add.v4.f32 [%0], {%1,%2,%3,%4};"
                     :: "l"(dst), "f"(y0), "f"(y1), "f"(y2), "f"(y3)
                     : "memory");
        if (lane == 0) atomicAdd(&g_cnt[c], 1);
    }
}

// ---------------- build h2in = concat(x, s/cnt) ------------------------------
__global__ void build_h2in(const float* __restrict__ x) {
    int idx = blockIdx.x * blockDim.x + threadIdx.x;
    int stride = gridDim.x * blockDim.x;
    const int total = N_NODES * 64;
    for (int i = idx; i < total; i += stride) {
        int n = i >> 6, q = i & 63;
        float4 v;
        if (q < 32) {
            v = ld4(x + (size_t)n * 128 + (q << 2));
        } else {
            int c = q - 32;
            v = ld4(g_s + (size_t)n * 128 + (c << 2));
            int cnt = g_cnt[n];
            float inv = (cnt > 0) ? (1.f / (float)cnt) : 0.f;
            v.x *= inv; v.y *= inv; v.z *= inv; v.w *= inv;
        }
        *reinterpret_cast<float4*>(g_h2in + (size_t)n * 256 + (q << 2)) = v;
    }
}

// ---------------- launch ------------------------------------------------------
extern "C" void kernel_launch(void* const* d_in, const int* in_sizes, int n_in,
                              void* d_out, int out_size)
{
    const float* x     = (const float*)d_in[0];
    const int*   eidx  = (const int*)  d_in[1];
    const float* eattr = (const float*)d_in[2];
    const float* W1  = (const float*)d_in[5];
    const float* b1  = (const float*)d_in[6];
    const float* g1  = (const float*)d_in[7];
    const float* be1 = (const float*)d_in[8];
    const float* W2  = (const float*)d_in[9];
    const float* b2  = (const float*)d_in[10];
    const float* g2  = (const float*)d_in[11];
    const float* be2 = (const float*)d_in[12];
    const float* Wl  = (const float*)d_in[13];
    const float* bl  = (const float*)d_in[14];
    float* out = (float*)d_out;

    const int* erow = eidx;
    const int* ecol = eidx + E_EDGES;

    cudaFuncSetAttribute(gemm1_mma, cudaFuncAttributeMaxDynamicSharedMemorySize, G3_TOT);
    cudaFuncSetAttribute(mma_gemm<2, 0, 0, 0>, cudaFuncAttributeMaxDynamicSharedMemorySize, Q_TOT);
    cudaFuncSetAttribute(mma_gemm<4, 1, 1, 1>, cudaFuncAttributeMaxDynamicSharedMemorySize, Q_TOT);
    cudaFuncSetAttribute(mma_gemm<4, 2, 2, 2>, cudaFuncAttributeMaxDynamicSharedMemorySize, Q_TOT);

    const int MB = (N_NODES + 127) / 128;   // 391

    // 0) zero accumulators + prep all weight images
    zero_kernel<<<2048, 256>>>();
    prep_W<<<480, 256>>>(W1, W2, Wl);

    // 1) P = x @ W1_top + b1
    mma_gemm<2, 0, 0, 0><<<dim3(MB, 1), 256, Q_TOT>>>(x, 128, N_NODES, b1, nullptr, 128);

    // 2) persistent fp16 1-pass, 3 CTAs/SM: Y = eattr @ W1_bot + P[row]
    gemm1_mma<<<G_GRID, 256, G3_TOT>>>(eattr, erow);

    // 3) BN1 scale/shift
    finalize_bn<<<1, 256>>>(g1, be1, 128, 1.f / (float)E_EDGES, 0);

    // 4) BN1 + ReLU + scatter (fp16 Y)
    scatter_kernel<<<2368, 256>>>(ecol);

    // 5) h2in = concat(x, s/cnt)
    build_h2in<<<2048, 256>>>(x);

    // 6) Z2 = h2in @ W2 + b2, fused BN2 stats
    mma_gemm<4, 1, 1, 1><<<dim3(MB, 2), 256, Q_TOT>>>(nullptr, 256, N_NODES, b2, nullptr, 256);

    // 7) BN2 scale/shift
    finalize_bn<<<1, 256>>>(g2, be2, 256, 1.f / (float)N_NODES, 1);

    // 8) out = relu(relu(bn2(Z2)) @ Wl + bl)
    mma_gemm<4, 2, 2, 2><<<dim3(MB, 1), 256, Q_TOT>>>(nullptr, 256, N_NODES, bl, out, 128);
}

// round 13
// speedup vs baseline: 1.3575x; 1.3575x over previous
#include <cuda_runtime.h>
#include <cuda_bf16.h>
#include <cuda_fp16.h>
#include <cstdint>

#define E_EDGES 1600000
#define N_NODES 50000
#define EPS_BN 1e-5f

// ---------------- scratch (device globals; no allocations allowed) ----------
__device__ __half g_Y[(size_t)E_EDGES * 128];     // pre-BN edge activations (fp16)
__device__ float g_P[(size_t)N_NODES * 128];      // x @ W1_top + b1
__device__ float g_s[(size_t)N_NODES * 128];      // scatter-sum accumulator
__device__ int   g_cnt[N_NODES];
__device__ float g_h2in[(size_t)N_NODES * 256];
__device__ float g_Z2[(size_t)N_NODES * 256];
__device__ float g_sum1[128], g_ssq1[128], g_scale1[128], g_shift1[128];
__device__ float g_sum2[256], g_ssq2[256], g_scale2[256], g_shift2[256];
// Weight images (padded rows, uint4-clean)
__device__ uint4 g_W1bH16[1088];                   // W1_bot fp16 [64 k][136 n]
__device__ uint4 g_W1tH[2176],    g_W1tL[2176];    // W1_top bf16 [128 k][136 n]
__device__ uint4 g_W2H[8448],     g_W2L[8448];     // W2    bf16 [256 k][264 n]
__device__ uint4 g_WlH[4352],     g_WlL[4352];     // Wl    bf16 [256 k][136 n]

__device__ __forceinline__ float4 ld4(const float* p) {
    return *reinterpret_cast<const float4*>(p);
}
__device__ __forceinline__ uint32_t smem_u32(const void* p) {
    uint32_t a;
    asm("{ .reg .u64 t; cvta.to.shared.u64 t, %1; cvt.u32.u64 %0, t; }" : "=r"(a) : "l"(p));
    return a;
}

// ---------------- warp MMA primitives (sm_80 baseline) ----------------------
__device__ __forceinline__ void mma_bf16(float* c, const uint32_t* a, const uint32_t* b) {
    asm volatile(
        "mma.sync.aligned.m16n8k16.row.col.f32.bf16.bf16.f32 "
        "{%0,%1,%2,%3}, {%4,%5,%6,%7}, {%8,%9}, {%0,%1,%2,%3};"
        : "+f"(c[0]), "+f"(c[1]), "+f"(c[2]), "+f"(c[3])
        : "r"(a[0]), "r"(a[1]), "r"(a[2]), "r"(a[3]), "r"(b[0]), "r"(b[1]));
}
__device__ __forceinline__ void mma_f16(float* c, const uint32_t* a, const uint32_t* b) {
    asm volatile(
        "mma.sync.aligned.m16n8k16.row.col.f32.f16.f16.f32 "
        "{%0,%1,%2,%3}, {%4,%5,%6,%7}, {%8,%9}, {%0,%1,%2,%3};"
        : "+f"(c[0]), "+f"(c[1]), "+f"(c[2]), "+f"(c[3])
        : "r"(a[0]), "r"(a[1]), "r"(a[2]), "r"(a[3]), "r"(b[0]), "r"(b[1]));
}
__device__ __forceinline__ void ldsm4(uint32_t* r, uint32_t addr) {
    asm volatile("ldmatrix.sync.aligned.m8n8.x4.shared.b16 {%0,%1,%2,%3}, [%4];"
        : "=r"(r[0]), "=r"(r[1]), "=r"(r[2]), "=r"(r[3]) : "r"(addr));
}
__device__ __forceinline__ void ldsm4t(uint32_t* r, uint32_t addr) {
    asm volatile("ldmatrix.sync.aligned.m8n8.x4.trans.shared.b16 {%0,%1,%2,%3}, [%4];"
        : "=r"(r[0]), "=r"(r[1]), "=r"(r[2]), "=r"(r[3]) : "r"(addr));
}
__device__ __forceinline__ void split_store(char* hi, char* lo, int j, float4 v) {
    __nv_bfloat16 h0 = __float2bfloat16_rn(v.x), h1 = __float2bfloat16_rn(v.y);
    __nv_bfloat16 h2 = __float2bfloat16_rn(v.z), h3 = __float2bfloat16_rn(v.w);
    __nv_bfloat162 hp0(h0, h1), hp1(h2, h3);
    __nv_bfloat162 lp0(__float2bfloat16_rn(v.x - __bfloat162float(h0)),
                       __float2bfloat16_rn(v.y - __bfloat162float(h1)));
    __nv_bfloat162 lp1(__float2bfloat16_rn(v.z - __bfloat162float(h2)),
                       __float2bfloat16_rn(v.w - __bfloat162float(h3)));
    *reinterpret_cast<uint2*>(hi + j * 8) =
        make_uint2(*reinterpret_cast<uint32_t*>(&hp0), *reinterpret_cast<uint32_t*>(&hp1));
    *reinterpret_cast<uint2*>(lo + j * 8) =
        make_uint2(*reinterpret_cast<uint32_t*>(&lp0), *reinterpret_cast<uint32_t*>(&lp1));
}
__device__ __forceinline__ void cp_async16(uint32_t saddr, const void* gptr) {
    asm volatile("cp.async.cg.shared.global [%0], [%1], 16;"
                 :: "r"(saddr), "l"(gptr) : "memory");
}
__device__ __forceinline__ void prefetchL1(const void* gptr) {
    asm volatile("prefetch.global.L1 [%0];" :: "l"(gptr));
}

// ---------------- zero scratch ----------------------------------------------
__global__ void zero_kernel() {
    int idx = blockIdx.x * blockDim.x + threadIdx.x;
    int stride = gridDim.x * blockDim.x;
    float4 z4 = make_float4(0.f, 0.f, 0.f, 0.f);
    int total4 = N_NODES * 32;
    float4* s4 = reinterpret_cast<float4*>(g_s);
    for (int i = idx; i < total4; i += stride) s4[i] = z4;
    for (int i = idx; i < N_NODES; i += stride) g_cnt[i] = 0;
    if (idx < 128) { g_sum1[idx] = 0.f; g_ssq1[idx] = 0.f; }
    if (idx < 256) { g_sum2[idx] = 0.f; g_ssq2[idx] = 0.f; }
}

// ---------------- prep: all weight images ------------------------------------
__global__ void prep_W(const float* __restrict__ W1, const float* __restrict__ W2,
                       const float* __restrict__ Wl) {
    int idx = blockIdx.x * blockDim.x + threadIdx.x;
    if (idx < 8192) {                       // W1_bot fp16: [64 k][128 n] -> 136
        int k = idx >> 7, n = idx & 127;
        float f = W1[(size_t)(128 + k) * 128 + n];
        __half h = __float2half_rn(f);
        reinterpret_cast<uint16_t*>(g_W1bH16)[k * 136 + n] = *reinterpret_cast<uint16_t*>(&h);
        return;
    }
    float f;
    uint16_t *dh, *dl;
    int off;
    if (idx < 24576) {                      // W1_top bf16: [128 k][128 n] -> 136
        int l = idx - 8192, k = l >> 7, n = l & 127;
        f = W1[(size_t)k * 128 + n];
        dh = reinterpret_cast<uint16_t*>(g_W1tH);
        dl = reinterpret_cast<uint16_t*>(g_W1tL);
        off = k * 136 + n;
    } else if (idx < 90112) {               // W2 bf16: [256 k][256 n] -> 264
        int l = idx - 24576, k = l >> 8, n = l & 255;
        f = W2[(size_t)k * 256 + n];
        dh = reinterpret_cast<uint16_t*>(g_W2H);
        dl = reinterpret_cast<uint16_t*>(g_W2L);
        off = k * 264 + n;
    } else if (idx < 122880) {              // Wl bf16: [256 k][128 n] -> 136
        int l = idx - 90112, k = l >> 7, n = l & 127;
        f = Wl[(size_t)k * 128 + n];
        dh = reinterpret_cast<uint16_t*>(g_WlH);
        dl = reinterpret_cast<uint16_t*>(g_WlL);
        off = k * 136 + n;
    } else return;
    __nv_bfloat16 h = __float2bfloat16_rn(f);
    __nv_bfloat16 l = __float2bfloat16_rn(f - __bfloat162float(h));
    dh[off] = *reinterpret_cast<uint16_t*>(&h);
    dl[off] = *reinterpret_cast<uint16_t*>(&l);
}

// ---------------- SMEM layouts ------------------------------------------------
// mma_gemm (bf16 3-pass, unchanged):
#define Q_AHI 0
#define Q_ALO 18432
#define Q_WHI 36864
#define Q_WLO 54272
#define Q_ROW 71680
#define Q_SUM 72192
#define Q_SSQ 72704
#define Q_TOT 73216
#define A_STRIDE 144
// gemm1 (fp16 single-pass, persistent, 2 CTAs/SM):
#define G3_A 0
#define G3_W 18432
#define G3_STAGE 35840       // raw eattr tile [128][272B] = 34816
#define G3_SROWSTG 70656
#define G3_SROW 71168
#define G3_SUM 71680
#define G3_SSQ 72192
#define G3_TOT 72704
#define G_GRID 296
#define G_NT (E_EDGES / 128)

// ---------------- gemm1 (persistent, fp16 1-pass): Y = eattr@W1_bot + P[row] --
__global__ void __launch_bounds__(256, 2)
gemm1_mma(const float* __restrict__ eattr, const int* __restrict__ erow) {
    extern __shared__ char smem[];
    const uint32_t sb = smem_u32(smem);
    const int tid = threadIdx.x, wid = tid >> 5, lane = tid & 31;

    // one-time: W fp16 image, stat init
    {
        uint4* dw = reinterpret_cast<uint4*>(smem + G3_W);
        for (int i = tid; i < 1088; i += 256) dw[i] = g_W1bH16[i];
    }
    if (tid < 128) {
        ((float*)(smem + G3_SUM))[tid] = 0.f;
        ((float*)(smem + G3_SSQ))[tid] = 0.f;
    }

    // prologue: stage first tile
    {
        int t0 = blockIdx.x;
        const char* src = (const char*)(eattr + (size_t)t0 * 128 * 64);
        #pragma unroll
        for (int i = tid; i < 2048; i += 256) {
            int r = i >> 4, q = i & 15;
            cp_async16(sb + G3_STAGE + r * 272 + q * 16, src + (size_t)r * 256 + q * 16);
        }
        if (tid < 32)
            cp_async16(sb + G3_SROWSTG + tid * 16,
                       (const char*)(erow + (size_t)t0 * 128) + tid * 16);
        asm volatile("cp.async.commit_group;" ::: "memory");
    }

    const int m0 = (wid & 3) * 32;
    const int n0 = (wid >> 2) * 64;
    const uint32_t aRowOff = (uint32_t)(m0 + (lane & 15)) * (uint32_t)A_STRIDE
                           + (uint32_t)(lane >> 4) * 16u;
    const uint32_t bOff = (uint32_t)((lane & 7) + ((lane >> 3) & 1) * 8) * 272u
                        + ((uint32_t)(lane >> 4) * 8u + (uint32_t)n0) * 2u;
    const int g = lane >> 2, t2 = (lane & 3) * 2;
    const int* s_row = (const int*)(smem + G3_SROW);
    float* s_sum = (float*)(smem + G3_SUM);
    float* s_ssq = (float*)(smem + G3_SSQ);

    float csum[8][2], cssq[8][2];
    #pragma unroll
    for (int ni = 0; ni < 8; ++ni) {
        csum[ni][0] = 0.f; csum[ni][1] = 0.f;
        cssq[ni][0] = 0.f; cssq[ni][1] = 0.f;
    }

    for (int t = blockIdx.x; t < G_NT; t += G_GRID) {
        asm volatile("cp.async.wait_group 0;" ::: "memory");
        __syncthreads();   // stage ready; prior MMA/epilogue done

        // convert stage -> single fp16 A image; publish erow
        {
            const int r = tid >> 1, h = tid & 1;
            const char* srow = smem + G3_STAGE + r * 272;
            char* ai = smem + G3_A + r * A_STRIDE;
            #pragma unroll
            for (int p = 0; p < 4; ++p) {
                int j = h * 8 + p * 2;
                float4 v0 = *reinterpret_cast<const float4*>(srow + j * 16);
                float4 v1 = *reinterpret_cast<const float4*>(srow + j * 16 + 16);
                __half2 a = __floats2half2_rn(v0.x, v0.y);
                __half2 b = __floats2half2_rn(v0.z, v0.w);
                __half2 c = __floats2half2_rn(v1.x, v1.y);
                __half2 d = __floats2half2_rn(v1.z, v1.w);
                uint4 pk = make_uint4(*reinterpret_cast<uint32_t*>(&a),
                                      *reinterpret_cast<uint32_t*>(&b),
                                      *reinterpret_cast<uint32_t*>(&c),
                                      *reinterpret_cast<uint32_t*>(&d));
                *reinterpret_cast<uint4*>(ai + j * 8) = pk;
            }
            if (tid < 128)
                ((int*)(smem + G3_SROW))[tid] = ((const int*)(smem + G3_SROWSTG))[tid];
        }
        __syncthreads();   // image + s_row visible; stage consumed

        // gather rows + P prefetch (hidden by MMA)
        int G00 = s_row[m0 + g],      G01 = s_row[m0 + g + 8];
        int G10 = s_row[m0 + 16 + g], G11 = s_row[m0 + 16 + g + 8];
        {
            const float* pb = g_P;
            prefetchL1(pb + (size_t)G00 * 128 + n0 + t2);
            prefetchL1(pb + (size_t)G00 * 128 + n0 + t2 + 32);
            prefetchL1(pb + (size_t)G01 * 128 + n0 + t2);
            prefetchL1(pb + (size_t)G01 * 128 + n0 + t2 + 32);
            prefetchL1(pb + (size_t)G10 * 128 + n0 + t2);
            prefetchL1(pb + (size_t)G10 * 128 + n0 + t2 + 32);
            prefetchL1(pb + (size_t)G11 * 128 + n0 + t2);
            prefetchL1(pb + (size_t)G11 * 128 + n0 + t2 + 32);
        }

        // stage next tile
        if (t + G_GRID < G_NT) {
            int tn = t + G_GRID;
            const char* src = (const char*)(eattr + (size_t)tn * 128 * 64);
            #pragma unroll
            for (int i = tid; i < 2048; i += 256) {
                int r = i >> 4, q = i & 15;
                cp_async16(sb + G3_STAGE + r * 272 + q * 16, src + (size_t)r * 256 + q * 16);
            }
            if (tid < 32)
                cp_async16(sb + G3_SROWSTG + tid * 16,
                           (const char*)(erow + (size_t)tn * 128) + tid * 16);
        }
        asm volatile("cp.async.commit_group;" ::: "memory");

        // ---- MMA: single fp16 pass ----
        float acc[2][8][4];
        #pragma unroll
        for (int mi = 0; mi < 2; ++mi)
            #pragma unroll
            for (int ni = 0; ni < 8; ++ni)
                #pragma unroll
                for (int c = 0; c < 4; ++c) acc[mi][ni][c] = 0.f;

        #pragma unroll
        for (int kt = 0; kt < 4; ++kt) {
            const uint32_t k0b = (uint32_t)kt * 32u;
            const uint32_t kwb = (uint32_t)kt * 4352u;
            uint32_t a0[4], a1[4];
            ldsm4(a0, sb + G3_A + aRowOff + k0b);
            ldsm4(a1, sb + G3_A + aRowOff + 16u * A_STRIDE + k0b);

            #pragma unroll
            for (int ni2 = 0; ni2 < 4; ++ni2) {
                uint32_t th[4];
                ldsm4t(th, sb + G3_W + bOff + kwb + (uint32_t)ni2 * 32u);
                mma_f16(acc[0][2 * ni2],     a0, th);
                mma_f16(acc[0][2 * ni2 + 1], a0, th + 2);
                mma_f16(acc[1][2 * ni2],     a1, th);
                mma_f16(acc[1][2 * ni2 + 1], a1, th + 2);
            }
        }

        // ---- epilogue: Y = Q + P[row] (L1-hot), fp16 streaming store --------
        const int mBase = t * 128;
        #pragma unroll
        for (int mi = 0; mi < 2; ++mi) {
            const int r0 = m0 + mi * 16 + g;
            const int G0 = (mi == 0) ? G00 : G10;
            const int G1 = (mi == 0) ? G01 : G11;
            const int row = mBase + r0;
            #pragma unroll
            for (int ni = 0; ni < 8; ++ni) {
                const int col = n0 + ni * 8 + t2;
                float2 p0 = *reinterpret_cast<const float2*>(g_P + (size_t)G0 * 128 + col);
                float2 p1 = *reinterpret_cast<const float2*>(g_P + (size_t)G1 * 128 + col);
                float y0 = acc[mi][ni][0] + p0.x;
                float y1 = acc[mi][ni][1] + p0.y;
                float y2 = acc[mi][ni][2] + p1.x;
                float y3 = acc[mi][ni][3] + p1.y;
                __half2 h01 = __floats2half2_rn(y0, y1);
                __half2 h23 = __floats2half2_rn(y2, y3);
                __stcs(reinterpret_cast<__half2*>(g_Y + (size_t)row * 128 + col), h01);
                __stcs(reinterpret_cast<__half2*>(g_Y + (size_t)(row + 8) * 128 + col), h23);
                csum[ni][0] += y0 + y2;
                csum[ni][1] += y1 + y3;
                cssq[ni][0] += y0 * y0 + y2 * y2;
                cssq[ni][1] += y1 * y1 + y3 * y3;
            }
        }
    }

    // ---- one-time BN1 stats reduction + global flush ----
    #pragma unroll
    for (int ni = 0; ni < 8; ++ni)
        #pragma unroll
        for (int par = 0; par < 2; ++par) {
            float s = csum[ni][par], q = cssq[ni][par];
            #pragma unroll
            for (int o = 4; o < 32; o <<= 1) {
                s += __shfl_xor_sync(0xFFFFFFFFu, s, o);
                q += __shfl_xor_sync(0xFFFFFFFFu, q, o);
            }
            if (g == 0) {
                atomicAdd(&s_sum[n0 + ni * 8 + t2 + par], s);
                atomicAdd(&s_ssq[n0 + ni * 8 + t2 + par], q);
            }
        }
    __syncthreads();
    if (tid < 128) {
        atomicAdd(&g_sum1[tid], s_sum[tid]);
        atomicAdd(&g_ssq1[tid], s_ssq[tid]);
    }
}

// ---------------- unified k-chunked bf16-split MMA GEMM (unchanged) ----------
// ASEL: 0=ext arg (x), 1=g_h2in, 2=g_Z2 (+bn2+relu transform)
// WSEL: 0=W1_top(17), 1=W2(33), 2=Wl(17)
// OSEL: 0=g_P, 1=g_Z2(+BN2 stats), 2=ext out arg(+relu)
template<int KCH, int ASEL, int WSEL, int OSEL>
__global__ void __launch_bounds__(256, 2)
mma_gemm(const float* __restrict__ Aext, int ldA, int M,
         const float* __restrict__ bias, float* __restrict__ outExt, int outLd)
{
    extern __shared__ char smem[];
    const uint32_t sb = smem_u32(smem);
    const int tid = threadIdx.x, wid = tid >> 5, lane = tid & 31;
    const int mBase = blockIdx.x * 128;
    const int nBase = blockIdx.y * 128;

    const float* A = (ASEL == 0) ? Aext : (ASEL == 1) ? (const float*)g_h2in
                                                      : (const float*)g_Z2;
    const uint4* WH = (WSEL == 0) ? g_W1tH : (WSEL == 1) ? g_W2H : g_WlH;
    const uint4* WL = (WSEL == 0) ? g_W1tL : (WSEL == 1) ? g_W2L : g_WlL;
    const int WR16 = (WSEL == 1) ? 33 : 17;
    float* outp = (OSEL == 0) ? (float*)g_P : (OSEL == 1) ? (float*)g_Z2 : outExt;

    if (tid < 128) {
        ((float*)(smem + Q_ROW))[tid] = bias[nBase + tid];
        ((float*)(smem + Q_SUM))[tid] = 0.f;
        ((float*)(smem + Q_SSQ))[tid] = 0.f;
    }

    const int m0 = (wid & 3) * 32;
    const int n0 = (wid >> 2) * 64;
    float acc[2][8][4];
    #pragma unroll
    for (int mi = 0; mi < 2; ++mi)
        #pragma unroll
        for (int ni = 0; ni < 8; ++ni)
            #pragma unroll
            for (int c = 0; c < 4; ++c) acc[mi][ni][c] = 0.f;

    const uint32_t aRowOff = (uint32_t)(m0 + (lane & 15)) * (uint32_t)A_STRIDE
                           + (uint32_t)(lane >> 4) * 16u;
    const uint32_t bOff = (uint32_t)((lane & 7) + ((lane >> 3) & 1) * 8) * 272u
                        + ((uint32_t)(lane >> 4) * 8u + (uint32_t)n0) * 2u;

    #pragma unroll 1
    for (int c = 0; c < KCH; ++c) {
        if (c) __syncthreads();
        {
            uint4* dh = reinterpret_cast<uint4*>(smem + Q_WHI);
            uint4* dl = reinterpret_cast<uint4*>(smem + Q_WLO);
            const uint4* sh = WH + (size_t)(c * 64) * WR16 + (nBase >> 3);
            const uint4* sl = WL + (size_t)(c * 64) * WR16 + (nBase >> 3);
            for (int i = tid; i < 1088; i += 256) {
                int kk = i / 17, q = i - kk * 17;
                dh[i] = sh[(size_t)kk * WR16 + q];
                dl[i] = sl[(size_t)kk * WR16 + q];
            }
        }
        {
            const int r = tid >> 1, h = tid & 1, rg = mBase + r;
            char* ahi = smem + Q_AHI + r * A_STRIDE;
            char* alo = smem + Q_ALO + r * A_STRIDE;
            const float4* ar = reinterpret_cast<const float4*>(A + (size_t)rg * ldA + c * 64);
            #pragma unroll
            for (int jj = 0; jj < 8; ++jj) {
                int j = h * 8 + jj;
                float4 v = make_float4(0.f, 0.f, 0.f, 0.f);
                if (rg < M) {
                    v = ar[j];
                    if (ASEL == 2) {
                        int kg = c * 64 + j * 4;
                        float4 sc = ld4(g_scale2 + kg), sh4 = ld4(g_shift2 + kg);
                        v.x = fmaxf(fmaf(v.x, sc.x, sh4.x), 0.f);
                        v.y = fmaxf(fmaf(v.y, sc.y, sh4.y), 0.f);
                        v.z = fmaxf(fmaf(v.z, sc.z, sh4.z), 0.f);
                        v.w = fmaxf(fmaf(v.w, sc.w, sh4.w), 0.f);
                    }
                }
                split_store(ahi, alo, j, v);
            }
        }
        __syncthreads();

        #pragma unroll
        for (int kt = 0; kt < 4; ++kt) {
            const uint32_t k0b = (uint32_t)kt * 32u;
            const uint32_t kwb = (uint32_t)kt * 4352u;
            uint32_t ah[2][4], al[2][4];
            ldsm4(ah[0], sb + Q_AHI + aRowOff + k0b);
            ldsm4(ah[1], sb + Q_AHI + aRowOff + 16u * A_STRIDE + k0b);
            ldsm4(al[0], sb + Q_ALO + aRowOff + k0b);
            ldsm4(al[1], sb + Q_ALO + aRowOff + 16u * A_STRIDE + k0b);

            #pragma unroll
            for (int ni2 = 0; ni2 < 4; ++ni2) {
                uint32_t th[4], tl[4];
                ldsm4t(th, sb + Q_WHI + bOff + kwb + (uint32_t)ni2 * 32u);
                ldsm4t(tl, sb + Q_WLO + bOff + kwb + (uint32_t)ni2 * 32u);
                #pragma unroll
                for (int mi = 0; mi < 2; ++mi) {
                    mma_bf16(acc[mi][2 * ni2],     ah[mi], th);
                    mma_bf16(acc[mi][2 * ni2],     al[mi], th);
                    mma_bf16(acc[mi][2 * ni2],     ah[mi], tl);
                    mma_bf16(acc[mi][2 * ni2 + 1], ah[mi], th + 2);
                    mma_bf16(acc[mi][2 * ni2 + 1], al[mi], th + 2);
                    mma_bf16(acc[mi][2 * ni2 + 1], ah[mi], tl + 2);
                }
            }
        }
    }
    __syncthreads();

    const float* bs = (const float*)(smem + Q_ROW);
    float* s_sum = (float*)(smem + Q_SUM);
    float* s_ssq = (float*)(smem + Q_SSQ);
    const int g = lane >> 2, t2 = (lane & 3) * 2;

    float csum[8][2], cssq[8][2];
    if (OSEL == 1) {
        #pragma unroll
        for (int ni = 0; ni < 8; ++ni) {
            csum[ni][0] = 0.f; csum[ni][1] = 0.f;
            cssq[ni][0] = 0.f; cssq[ni][1] = 0.f;
        }
    }

    #pragma unroll
    for (int mi = 0; mi < 2; ++mi) {
        const int row = mBase + m0 + mi * 16 + g;
        const bool v0 = row < M, v1 = (row + 8) < M;
        #pragma unroll
        for (int ni = 0; ni < 8; ++ni) {
            const int col = n0 + ni * 8 + t2;
            float b0 = bs[col], b1 = bs[col + 1];
            float y0 = acc[mi][ni][0] + b0;
            float y1 = acc[mi][ni][1] + b1;
            float y2 = acc[mi][ni][2] + b0;
            float y3 = acc[mi][ni][3] + b1;
            if (OSEL == 2) {
                y0 = fmaxf(y0, 0.f); y1 = fmaxf(y1, 0.f);
                y2 = fmaxf(y2, 0.f); y3 = fmaxf(y3, 0.f);
            }
            if (v0)
                *reinterpret_cast<float2*>(outp + (size_t)row * outLd + nBase + col)
                    = make_float2(y0, y1);
            if (v1)
                *reinterpret_cast<float2*>(outp + (size_t)(row + 8) * outLd + nBase + col)
                    = make_float2(y2, y3);
            if (OSEL == 1) {
                if (v0) {
                    csum[ni][0] += y0; csum[ni][1] += y1;
                    cssq[ni][0] += y0 * y0; cssq[ni][1] += y1 * y1;
                }
                if (v1) {
                    csum[ni][0] += y2; csum[ni][1] += y3;
                    cssq[ni][0] += y2 * y2; cssq[ni][1] += y3 * y3;
                }
            }
        }
    }
    if (OSEL == 1) {
        #pragma unroll
        for (int ni = 0; ni < 8; ++ni)
            #pragma unroll
            for (int par = 0; par < 2; ++par) {
                float s = csum[ni][par], q = cssq[ni][par];
                #pragma unroll
                for (int o = 4; o < 32; o <<= 1) {
                    s += __shfl_xor_sync(0xFFFFFFFFu, s, o);
                    q += __shfl_xor_sync(0xFFFFFFFFu, q, o);
                }
                if (g == 0) {
                    atomicAdd(&s_sum[n0 + ni * 8 + t2 + par], s);
                    atomicAdd(&s_ssq[n0 + ni * 8 + t2 + par], q);
                }
            }
        __syncthreads();
        if (tid < 128) {
            atomicAdd(&g_sum2[nBase + tid], s_sum[tid]);
            atomicAdd(&g_ssq2[nBase + tid], s_ssq[tid]);
        }
    }
}

// ---------------- BN finalize -------------------------------------------------
__global__ void finalize_bn(const float* __restrict__ gamma,
                            const float* __restrict__ beta,
                            int C, float invM, int which)
{
    int i = blockIdx.x * blockDim.x + threadIdx.x;
    if (i < C) {
        const float* sum = (which == 0) ? g_sum1 : g_sum2;
        const float* ssq = (which == 0) ? g_ssq1 : g_ssq2;
        float*     scale = (which == 0) ? g_scale1 : g_scale2;
        float*     shift = (which == 0) ? g_shift1 : g_shift2;
        float mu  = sum[i] * invM;
        float var = ssq[i] * invM - mu * mu;
        float inv = rsqrtf(var + EPS_BN);
        float sc  = gamma[i] * inv;
        scale[i] = sc;
        shift[i] = beta[i] - mu * sc;
    }
}

// ---------------- BN+ReLU then scatter-add (fp16 Y, vector atomics) ----------
__global__ void scatter_kernel(const int* __restrict__ ecol) {
    const int lane   = threadIdx.x & 31;
    const int warp   = (blockIdx.x * blockDim.x + threadIdx.x) >> 5;
    const int nWarps = (gridDim.x * blockDim.x) >> 5;

    float4 sc = *reinterpret_cast<const float4*>(&g_scale1[lane << 2]);
    float4 sh = *reinterpret_cast<const float4*>(&g_shift1[lane << 2]);

    for (int e = warp; e < E_EDGES; e += nWarps) {
        int c = ecol[e];
        uint2 raw = __ldcs(reinterpret_cast<const uint2*>(&g_Y[(size_t)e * 128 + (lane << 2)]));
        __half2 ha = *reinterpret_cast<__half2*>(&raw.x);
        __half2 hb = *reinterpret_cast<__half2*>(&raw.y);
        float2 f01 = __half22float2(ha);
        float2 f23 = __half22float2(hb);
        float y0 = fmaxf(fmaf(f01.x, sc.x, sh.x), 0.f);
        float y1 = fmaxf(fmaf(f01.y, sc.y, sh.y), 0.f);
        float y2 = fmaxf(fmaf(f23.x, sc.z, sh.z), 0.f);
        float y3 = fmaxf(fmaf(f23.y, sc.w, sh.w), 0.f);
        float* dst = &g_s[(size_t)c * 128 + (lane << 2)];
        asm volatile("red.global.add.v4.f32 [%0], {%1,%2,%3,%4};"
                     :: "l"(dst), "f"(y0), "f"(y1), "f"(y2), "f"(y3)
                     : "memory");
        if (lane == 0) atomicAdd(&g_cnt[c], 1);
    }
}

// ---------------- build h2in = concat(x, s/cnt) ------------------------------
__global__ void build_h2in(const float* __restrict__ x) {
    int idx = blockIdx.x * blockDim.x + threadIdx.x;
    int stride = gridDim.x * blockDim.x;
    const int total = N_NODES * 64;
    for (int i = idx; i < total; i += stride) {
        int n = i >> 6, q = i & 63;
        float4 v;
        if (q < 32) {
            v = ld4(x + (size_t)n * 128 + (q << 2));
        } else {
            int c = q - 32;
            v = ld4(g_s + (size_t)n * 128 + (c << 2));
            int cnt = g_cnt[n];
            float inv = (cnt > 0) ? (1.f / (float)cnt) : 0.f;
            v.x *= inv; v.y *= inv; v.z *= inv; v.w *= inv;
        }
        *reinterpret_cast<float4*>(g_h2in + (size_t)n * 256 + (q << 2)) = v;
    }
}

// ---------------- launch ------------------------------------------------------
extern "C" void kernel_launch(void* const* d_in, const int* in_sizes, int n_in,
                              void* d_out, int out_size)
{
    const float* x     = (const float*)d_in[0];
    const int*   eidx  = (const int*)  d_in[1];
    const float* eattr = (const float*)d_in[2];
    const float* W1  = (const float*)d_in[5];
    const float* b1  = (const float*)d_in[6];
    const float* g1  = (const float*)d_in[7];
    const float* be1 = (const float*)d_in[8];
    const float* W2  = (const float*)d_in[9];
    const float* b2  = (const float*)d_in[10];
    const float* g2  = (const float*)d_in[11];
    const float* be2 = (const float*)d_in[12];
    const float* Wl  = (const float*)d_in[13];
    const float* bl  = (const float*)d_in[14];
    float* out = (float*)d_out;

    const int* erow = eidx;
    const int* ecol = eidx + E_EDGES;

    cudaFuncSetAttribute(gemm1_mma, cudaFuncAttributeMaxDynamicSharedMemorySize, G3_TOT);
    cudaFuncSetAttribute(mma_gemm<2, 0, 0, 0>, cudaFuncAttributeMaxDynamicSharedMemorySize, Q_TOT);
    cudaFuncSetAttribute(mma_gemm<4, 1, 1, 1>, cudaFuncAttributeMaxDynamicSharedMemorySize, Q_TOT);
    cudaFuncSetAttribute(mma_gemm<4, 2, 2, 2>, cudaFuncAttributeMaxDynamicSharedMemorySize, Q_TOT);

    const int MB = (N_NODES + 127) / 128;   // 391

    // 0) zero accumulators + prep all weight images
    zero_kernel<<<2048, 256>>>();
    prep_W<<<480, 256>>>(W1, W2, Wl);

    // 1) P = x @ W1_top + b1
    mma_gemm<2, 0, 0, 0><<<dim3(MB, 1), 256, Q_TOT>>>(x, 128, N_NODES, b1, nullptr, 128);

    // 2) persistent fp16 1-pass, 2 CTAs/SM: Y = eattr @ W1_bot + P[row]
    gemm1_mma<<<G_GRID, 256, G3_TOT>>>(eattr, erow);

    // 3) BN1 scale/shift
    finalize_bn<<<1, 256>>>(g1, be1, 128, 1.f / (float)E_EDGES, 0);

    // 4) BN1 + ReLU + scatter (fp16 Y)
    scatter_kernel<<<2368, 256>>>(ecol);

    // 5) h2in = concat(x, s/cnt)
    build_h2in<<<2048, 256>>>(x);

    // 6) Z2 = h2in @ W2 + b2, fused BN2 stats
    mma_gemm<4, 1, 1, 1><<<dim3(MB, 2), 256, Q_TOT>>>(nullptr, 256, N_NODES, b2, nullptr, 256);

    // 7) BN2 scale/shift
    finalize_bn<<<1, 256>>>(g2, be2, 256, 1.f / (float)N_NODES, 1);

    // 8) out = relu(relu(bn2(Z2)) @ Wl + bl)
    mma_gemm<4, 2, 2, 2><<<dim3(MB, 1), 256, Q_TOT>>>(nullptr, 256, N_NODES, bl, out, 128);
}

// round 15
// speedup vs baseline: 1.4165x; 1.0434x over previous
#include <cuda_runtime.h>
#include <cuda_bf16.h>
#include <cuda_fp16.h>
#include <cstdint>

#define E_EDGES 1600000
#define N_NODES 50000
#define EPS_BN 1e-5f

// ---------------- scratch (device globals; no allocations allowed) ----------
__device__ __half g_Y[(size_t)E_EDGES * 128];     // pre-BN edge activations (fp16)
__device__ float g_P[(size_t)N_NODES * 128];      // x @ W1_top + b1
__device__ float g_s[(size_t)N_NODES * 128];      // scatter-sum accumulator
__device__ int   g_cnt[N_NODES];
__device__ float g_Z2[(size_t)N_NODES * 256];
__device__ float g_sum1[128], g_ssq1[128], g_scale1[128], g_shift1[128];
__device__ float g_sum2[256], g_ssq2[256], g_scale2[256], g_shift2[256];
__device__ float g_blv[128];                       // final-layer bias
// Weight images (padded rows, uint4-clean)
__device__ uint4 g_W1bH16[1088];                   // W1_bot fp16 [64 k][136 n]
__device__ uint4 g_W1tH16[2176];                   // W1_top fp16 [128 k][136 n]
__device__ uint4 g_W2H16[8448];                    // W2 fp16 [256 k][264 n]
__device__ uint4 g_WlH[4352],  g_WlL[4352];        // Wl bf16 hi/lo [256 k][136 n]

__device__ __forceinline__ float4 ld4(const float* p) {
    return *reinterpret_cast<const float4*>(p);
}
__device__ __forceinline__ uint32_t smem_u32(const void* p) {
    uint32_t a;
    asm("{ .reg .u64 t; cvta.to.shared.u64 t, %1; cvt.u32.u64 %0, t; }" : "=r"(a) : "l"(p));
    return a;
}

// ---------------- warp MMA primitives (sm_80 baseline) ----------------------
__device__ __forceinline__ void mma_bf16(float* c, const uint32_t* a, const uint32_t* b) {
    asm volatile(
        "mma.sync.aligned.m16n8k16.row.col.f32.bf16.bf16.f32 "
        "{%0,%1,%2,%3}, {%4,%5,%6,%7}, {%8,%9}, {%0,%1,%2,%3};"
        : "+f"(c[0]), "+f"(c[1]), "+f"(c[2]), "+f"(c[3])
        : "r"(a[0]), "r"(a[1]), "r"(a[2]), "r"(a[3]), "r"(b[0]), "r"(b[1]));
}
__device__ __forceinline__ void mma_f16(float* c, const uint32_t* a, const uint32_t* b) {
    asm volatile(
        "mma.sync.aligned.m16n8k16.row.col.f32.f16.f16.f32 "
        "{%0,%1,%2,%3}, {%4,%5,%6,%7}, {%8,%9}, {%0,%1,%2,%3};"
        : "+f"(c[0]), "+f"(c[1]), "+f"(c[2]), "+f"(c[3])
        : "r"(a[0]), "r"(a[1]), "r"(a[2]), "r"(a[3]), "r"(b[0]), "r"(b[1]));
}
__device__ __forceinline__ void ldsm4(uint32_t* r, uint32_t addr) {
    asm volatile("ldmatrix.sync.aligned.m8n8.x4.shared.b16 {%0,%1,%2,%3}, [%4];"
        : "=r"(r[0]), "=r"(r[1]), "=r"(r[2]), "=r"(r[3]) : "r"(addr));
}
__device__ __forceinline__ void ldsm4t(uint32_t* r, uint32_t addr) {
    asm volatile("ldmatrix.sync.aligned.m8n8.x4.trans.shared.b16 {%0,%1,%2,%3}, [%4];"
        : "=r"(r[0]), "=r"(r[1]), "=r"(r[2]), "=r"(r[3]) : "r"(addr));
}
__device__ __forceinline__ void split_store(char* hi, char* lo, int j, float4 v) {
    __nv_bfloat16 h0 = __float2bfloat16_rn(v.x), h1 = __float2bfloat16_rn(v.y);
    __nv_bfloat16 h2 = __float2bfloat16_rn(v.z), h3 = __float2bfloat16_rn(v.w);
    __nv_bfloat162 hp0(h0, h1), hp1(h2, h3);
    __nv_bfloat162 lp0(__float2bfloat16_rn(v.x - __bfloat162float(h0)),
                       __float2bfloat16_rn(v.y - __bfloat162float(h1)));
    __nv_bfloat162 lp1(__float2bfloat16_rn(v.z - __bfloat162float(h2)),
                       __float2bfloat16_rn(v.w - __bfloat162float(h3)));
    *reinterpret_cast<uint2*>(hi + j * 8) =
        make_uint2(*reinterpret_cast<uint32_t*>(&hp0), *reinterpret_cast<uint32_t*>(&hp1));
    *reinterpret_cast<uint2*>(lo + j * 8) =
        make_uint2(*reinterpret_cast<uint32_t*>(&lp0), *reinterpret_cast<uint32_t*>(&lp1));
}
__device__ __forceinline__ void pack_f16_store(char* ai, int j, float4 v0, float4 v1) {
    __half2 a = __floats2half2_rn(v0.x, v0.y);
    __half2 b = __floats2half2_rn(v0.z, v0.w);
    __half2 c = __floats2half2_rn(v1.x, v1.y);
    __half2 d = __floats2half2_rn(v1.z, v1.w);
    *reinterpret_cast<uint4*>(ai + j * 8) =
        make_uint4(*reinterpret_cast<uint32_t*>(&a), *reinterpret_cast<uint32_t*>(&b),
                   *reinterpret_cast<uint32_t*>(&c), *reinterpret_cast<uint32_t*>(&d));
}
__device__ __forceinline__ void cp_async16(uint32_t saddr, const void* gptr) {
    asm volatile("cp.async.cg.shared.global [%0], [%1], 16;"
                 :: "r"(saddr), "l"(gptr) : "memory");
}
__device__ __forceinline__ void prefetchL1(const void* gptr) {
    asm volatile("prefetch.global.L1 [%0];" :: "l"(gptr));
}

// ---------------- zero scratch ----------------------------------------------
__global__ void zero_kernel() {
    int idx = blockIdx.x * blockDim.x + threadIdx.x;
    int stride = gridDim.x * blockDim.x;
    float4 z4 = make_float4(0.f, 0.f, 0.f, 0.f);
    int total4 = N_NODES * 32;
    float4* s4 = reinterpret_cast<float4*>(g_s);
    for (int i = idx; i < total4; i += stride) s4[i] = z4;
    for (int i = idx; i < N_NODES; i += stride) g_cnt[i] = 0;
    if (idx < 128) { g_sum1[idx] = 0.f; g_ssq1[idx] = 0.f; }
    if (idx < 256) { g_sum2[idx] = 0.f; g_ssq2[idx] = 0.f; }
}

// ---------------- prep: all weight images + final bias ------------------------
__global__ void prep_W(const float* __restrict__ W1, const float* __restrict__ W2,
                       const float* __restrict__ Wl, const float* __restrict__ bl) {
    int idx = blockIdx.x * blockDim.x + threadIdx.x;
    if (idx < 8192) {                       // W1_bot fp16: [64 k][128 n] -> 136
        int k = idx >> 7, n = idx & 127;
        __half h = __float2half_rn(W1[(size_t)(128 + k) * 128 + n]);
        reinterpret_cast<uint16_t*>(g_W1bH16)[k * 136 + n] = *reinterpret_cast<uint16_t*>(&h);
        if (idx < 128) g_blv[idx] = bl[idx];
    } else if (idx < 24576) {               // W1_top fp16: [128 k][128 n] -> 136
        int l = idx - 8192, k = l >> 7, n = l & 127;
        __half h = __float2half_rn(W1[(size_t)k * 128 + n]);
        reinterpret_cast<uint16_t*>(g_W1tH16)[k * 136 + n] = *reinterpret_cast<uint16_t*>(&h);
    } else if (idx < 90112) {               // W2 fp16: [256 k][256 n] -> 264
        int l = idx - 24576, k = l >> 8, n = l & 255;
        __half h = __float2half_rn(W2[(size_t)k * 256 + n]);
        reinterpret_cast<uint16_t*>(g_W2H16)[k * 264 + n] = *reinterpret_cast<uint16_t*>(&h);
    } else if (idx < 122880) {              // Wl bf16 hi/lo: [256 k][128 n] -> 136
        int l = idx - 90112, k = l >> 7, n = l & 127;
        float f = Wl[(size_t)k * 128 + n];
        __nv_bfloat16 h = __float2bfloat16_rn(f);
        __nv_bfloat16 lo = __float2bfloat16_rn(f - __bfloat162float(h));
        reinterpret_cast<uint16_t*>(g_WlH)[k * 136 + n] = *reinterpret_cast<uint16_t*>(&h);
        reinterpret_cast<uint16_t*>(g_WlL)[k * 136 + n] = *reinterpret_cast<uint16_t*>(&lo);
    }
}

// ---------------- SMEM layouts ------------------------------------------------
#define A_STRIDE 144
// final bf16 3-pass GEMM:
#define Q_AHI 0
#define Q_ALO 18432
#define Q_WHI 36864
#define Q_WLO 54272
#define Q_TOT 73216
// fp16 single-pass node GEMM:
#define M_A 0
#define M_W 18432
#define M_BIAS 35840
#define M_SUM 36352
#define M_SSQ 36864
#define M_TOT 37376
// gemm1 (fp16 single-pass, persistent, 2 CTAs/SM):
#define G3_A 0
#define G3_W 18432
#define G3_STAGE 35840
#define G3_SROWSTG 70656
#define G3_SROW 71168
#define G3_SUM 71680
#define G3_SSQ 72192
#define G3_TOT 72704
#define G_GRID 296
#define G_NT (E_EDGES / 128)

// ---------------- gemm1 (persistent, fp16 1-pass): Y = eattr@W1_bot + P[row] --
__global__ void __launch_bounds__(256, 2)
gemm1_mma(const float* __restrict__ eattr, const int* __restrict__ erow) {
    extern __shared__ char smem[];
    const uint32_t sb = smem_u32(smem);
    const int tid = threadIdx.x, wid = tid >> 5, lane = tid & 31;

    {
        uint4* dw = reinterpret_cast<uint4*>(smem + G3_W);
        for (int i = tid; i < 1088; i += 256) dw[i] = g_W1bH16[i];
    }
    if (tid < 128) {
        ((float*)(smem + G3_SUM))[tid] = 0.f;
        ((float*)(smem + G3_SSQ))[tid] = 0.f;
    }

    {
        int t0 = blockIdx.x;
        const char* src = (const char*)(eattr + (size_t)t0 * 128 * 64);
        #pragma unroll
        for (int i = tid; i < 2048; i += 256) {
            int r = i >> 4, q = i & 15;
            cp_async16(sb + G3_STAGE + r * 272 + q * 16, src + (size_t)r * 256 + q * 16);
        }
        if (tid < 32)
            cp_async16(sb + G3_SROWSTG + tid * 16,
                       (const char*)(erow + (size_t)t0 * 128) + tid * 16);
        asm volatile("cp.async.commit_group;" ::: "memory");
    }

    const int m0 = (wid & 3) * 32;
    const int n0 = (wid >> 2) * 64;
    const uint32_t aRowOff = (uint32_t)(m0 + (lane & 15)) * (uint32_t)A_STRIDE
                           + (uint32_t)(lane >> 4) * 16u;
    const uint32_t bOff = (uint32_t)((lane & 7) + ((lane >> 3) & 1) * 8) * 272u
                        + ((uint32_t)(lane >> 4) * 8u + (uint32_t)n0) * 2u;
    const int g = lane >> 2, t2 = (lane & 3) * 2;
    const int* s_row = (const int*)(smem + G3_SROW);
    float* s_sum = (float*)(smem + G3_SUM);
    float* s_ssq = (float*)(smem + G3_SSQ);

    float csum[8][2], cssq[8][2];
    #pragma unroll
    for (int ni = 0; ni < 8; ++ni) {
        csum[ni][0] = 0.f; csum[ni][1] = 0.f;
        cssq[ni][0] = 0.f; cssq[ni][1] = 0.f;
    }

    for (int t = blockIdx.x; t < G_NT; t += G_GRID) {
        asm volatile("cp.async.wait_group 0;" ::: "memory");
        __syncthreads();

        {
            const int r = tid >> 1, h = tid & 1;
            const char* srow = smem + G3_STAGE + r * 272;
            char* ai = smem + G3_A + r * A_STRIDE;
            #pragma unroll
            for (int p = 0; p < 4; ++p) {
                int j = h * 8 + p * 2;
                float4 v0 = *reinterpret_cast<const float4*>(srow + j * 16);
                float4 v1 = *reinterpret_cast<const float4*>(srow + j * 16 + 16);
                pack_f16_store(ai, j, v0, v1);
            }
            if (tid < 128)
                ((int*)(smem + G3_SROW))[tid] = ((const int*)(smem + G3_SROWSTG))[tid];
        }
        __syncthreads();

        int G00 = s_row[m0 + g],      G01 = s_row[m0 + g + 8];
        int G10 = s_row[m0 + 16 + g], G11 = s_row[m0 + 16 + g + 8];
        {
            const float* pb = g_P;
            prefetchL1(pb + (size_t)G00 * 128 + n0 + t2);
            prefetchL1(pb + (size_t)G00 * 128 + n0 + t2 + 32);
            prefetchL1(pb + (size_t)G01 * 128 + n0 + t2);
            prefetchL1(pb + (size_t)G01 * 128 + n0 + t2 + 32);
            prefetchL1(pb + (size_t)G10 * 128 + n0 + t2);
            prefetchL1(pb + (size_t)G10 * 128 + n0 + t2 + 32);
            prefetchL1(pb + (size_t)G11 * 128 + n0 + t2);
            prefetchL1(pb + (size_t)G11 * 128 + n0 + t2 + 32);
        }

        if (t + G_GRID < G_NT) {
            int tn = t + G_GRID;
            const char* src = (const char*)(eattr + (size_t)tn * 128 * 64);
            #pragma unroll
            for (int i = tid; i < 2048; i += 256) {
                int r = i >> 4, q = i & 15;
                cp_async16(sb + G3_STAGE + r * 272 + q * 16, src + (size_t)r * 256 + q * 16);
            }
            if (tid < 32)
                cp_async16(sb + G3_SROWSTG + tid * 16,
                           (const char*)(erow + (size_t)tn * 128) + tid * 16);
        }
        asm volatile("cp.async.commit_group;" ::: "memory");

        float acc[2][8][4];
        #pragma unroll
        for (int mi = 0; mi < 2; ++mi)
            #pragma unroll
            for (int ni = 0; ni < 8; ++ni)
                #pragma unroll
                for (int c = 0; c < 4; ++c) acc[mi][ni][c] = 0.f;

        #pragma unroll
        for (int kt = 0; kt < 4; ++kt) {
            const uint32_t k0b = (uint32_t)kt * 32u;
            const uint32_t kwb = (uint32_t)kt * 4352u;
            uint32_t a0[4], a1[4];
            ldsm4(a0, sb + G3_A + aRowOff + k0b);
            ldsm4(a1, sb + G3_A + aRowOff + 16u * A_STRIDE + k0b);

            #pragma unroll
            for (int ni2 = 0; ni2 < 4; ++ni2) {
                uint32_t th[4];
                ldsm4t(th, sb + G3_W + bOff + kwb + (uint32_t)ni2 * 32u);
                mma_f16(acc[0][2 * ni2],     a0, th);
                mma_f16(acc[0][2 * ni2 + 1], a0, th + 2);
                mma_f16(acc[1][2 * ni2],     a1, th);
                mma_f16(acc[1][2 * ni2 + 1], a1, th + 2);
            }
        }

        const int mBase = t * 128;
        #pragma unroll
        for (int mi = 0; mi < 2; ++mi) {
            const int r0 = m0 + mi * 16 + g;
            const int G0 = (mi == 0) ? G00 : G10;
            const int G1 = (mi == 0) ? G01 : G11;
            const int row = mBase + r0;
            #pragma unroll
            for (int ni = 0; ni < 8; ++ni) {
                const int col = n0 + ni * 8 + t2;
                float2 p0 = *reinterpret_cast<const float2*>(g_P + (size_t)G0 * 128 + col);
                float2 p1 = *reinterpret_cast<const float2*>(g_P + (size_t)G1 * 128 + col);
                float y0 = acc[mi][ni][0] + p0.x;
                float y1 = acc[mi][ni][1] + p0.y;
                float y2 = acc[mi][ni][2] + p1.x;
                float y3 = acc[mi][ni][3] + p1.y;
                __half2 h01 = __floats2half2_rn(y0, y1);
                __half2 h23 = __floats2half2_rn(y2, y3);
                __stcs(reinterpret_cast<__half2*>(g_Y + (size_t)row * 128 + col), h01);
                __stcs(reinterpret_cast<__half2*>(g_Y + (size_t)(row + 8) * 128 + col), h23);
                csum[ni][0] += y0 + y2;
                csum[ni][1] += y1 + y3;
                cssq[ni][0] += y0 * y0 + y2 * y2;
                cssq[ni][1] += y1 * y1 + y3 * y3;
            }
        }
    }

    #pragma unroll
    for (int ni = 0; ni < 8; ++ni)
        #pragma unroll
        for (int par = 0; par < 2; ++par) {
            float s = csum[ni][par], q = cssq[ni][par];
            #pragma unroll
            for (int o = 4; o < 32; o <<= 1) {
                s += __shfl_xor_sync(0xFFFFFFFFu, s, o);
                q += __shfl_xor_sync(0xFFFFFFFFu, q, o);
            }
            if (g == 0) {
                atomicAdd(&s_sum[n0 + ni * 8 + t2 + par], s);
                atomicAdd(&s_ssq[n0 + ni * 8 + t2 + par], q);
            }
        }
    __syncthreads();
    if (tid < 128) {
        atomicAdd(&g_sum1[tid], s_sum[tid]);
        atomicAdd(&g_ssq1[tid], s_ssq[tid]);
    }
}

// ---------------- fp16 single-pass node GEMM ---------------------------------
// ASEL 0: A = x [M,128] (KCH=2), out = g_P (+bias)
// ASEL 1: A = concat(x, g_s/cnt) [M,256] (KCH=4), out = g_Z2 (+bias, BN2 stats)
template<int KCH, int ASEL>
__global__ void __launch_bounds__(256, 2)
mma16_gemm(const float* __restrict__ x, int M, const float* __restrict__ bias)
{
    extern __shared__ char smem[];
    const uint32_t sb = smem_u32(smem);
    const int tid = threadIdx.x, wid = tid >> 5, lane = tid & 31;
    const int mBase = blockIdx.x * 128;
    const int nBase = blockIdx.y * 128;

    const uint4* WH = (ASEL == 0) ? g_W1tH16 : g_W2H16;
    const int WR16 = (ASEL == 0) ? 17 : 33;
    float* outp = (ASEL == 0) ? (float*)g_P : (float*)g_Z2;
    const int outLd = (ASEL == 0) ? 128 : 256;

    if (tid < 128) {
        ((float*)(smem + M_BIAS))[tid] = bias[nBase + tid];
        ((float*)(smem + M_SUM))[tid] = 0.f;
        ((float*)(smem + M_SSQ))[tid] = 0.f;
    }

    const int m0 = (wid & 3) * 32;
    const int n0 = (wid >> 2) * 64;
    float acc[2][8][4];
    #pragma unroll
    for (int mi = 0; mi < 2; ++mi)
        #pragma unroll
        for (int ni = 0; ni < 8; ++ni)
            #pragma unroll
            for (int c = 0; c < 4; ++c) acc[mi][ni][c] = 0.f;

    const uint32_t aRowOff = (uint32_t)(m0 + (lane & 15)) * (uint32_t)A_STRIDE
                           + (uint32_t)(lane >> 4) * 16u;
    const uint32_t bOff = (uint32_t)((lane & 7) + ((lane >> 3) & 1) * 8) * 272u
                        + ((uint32_t)(lane >> 4) * 8u + (uint32_t)n0) * 2u;

    #pragma unroll 1
    for (int c = 0; c < KCH; ++c) {
        if (c) __syncthreads();
        {
            uint4* dw = reinterpret_cast<uint4*>(smem + M_W);
            const uint4* sh = WH + (size_t)(c * 64) * WR16 + (nBase >> 3);
            for (int i = tid; i < 1088; i += 256) {
                int kk = i / 17, q = i - kk * 17;
                dw[i] = sh[(size_t)kk * WR16 + q];
            }
        }
        {
            const int r = tid >> 1, h = tid & 1, rg = mBase + r;
            char* ai = smem + M_A + r * A_STRIDE;
            float invc = 0.f;
            if (ASEL == 1 && c >= 2 && rg < M) {
                int ct = g_cnt[rg];
                invc = (ct > 0) ? (1.f / (float)ct) : 0.f;
            }
            const float* base =
                (ASEL == 0) ? (x + (size_t)rg * 128 + c * 64)
                            : (c < 2 ? (x + (size_t)rg * 128 + c * 64)
                                     : ((const float*)g_s + (size_t)rg * 128 + (c - 2) * 64));
            #pragma unroll
            for (int p = 0; p < 4; ++p) {
                int j = h * 8 + p * 2;
                float4 v0 = make_float4(0.f, 0.f, 0.f, 0.f);
                float4 v1 = make_float4(0.f, 0.f, 0.f, 0.f);
                if (rg < M) {
                    v0 = ld4(base + j * 4);
                    v1 = ld4(base + j * 4 + 4);
                    if (ASEL == 1 && c >= 2) {
                        v0.x *= invc; v0.y *= invc; v0.z *= invc; v0.w *= invc;
                        v1.x *= invc; v1.y *= invc; v1.z *= invc; v1.w *= invc;
                    }
                }
                pack_f16_store(ai, j, v0, v1);
            }
        }
        __syncthreads();

        #pragma unroll
        for (int kt = 0; kt < 4; ++kt) {
            const uint32_t k0b = (uint32_t)kt * 32u;
            const uint32_t kwb = (uint32_t)kt * 4352u;
            uint32_t a0[4], a1[4];
            ldsm4(a0, sb + M_A + aRowOff + k0b);
            ldsm4(a1, sb + M_A + aRowOff + 16u * A_STRIDE + k0b);
            #pragma unroll
            for (int ni2 = 0; ni2 < 4; ++ni2) {
                uint32_t th[4];
                ldsm4t(th, sb + M_W + bOff + kwb + (uint32_t)ni2 * 32u);
                mma_f16(acc[0][2 * ni2],     a0, th);
                mma_f16(acc[0][2 * ni2 + 1], a0, th + 2);
                mma_f16(acc[1][2 * ni2],     a1, th);
                mma_f16(acc[1][2 * ni2 + 1], a1, th + 2);
            }
        }
    }
    __syncthreads();

    const float* bs = (const float*)(smem + M_BIAS);
    float* s_sum = (float*)(smem + M_SUM);
    float* s_ssq = (float*)(smem + M_SSQ);
    const int g = lane >> 2, t2 = (lane & 3) * 2;

    float csum[8][2], cssq[8][2];
    if (ASEL == 1) {
        #pragma unroll
        for (int ni = 0; ni < 8; ++ni) {
            csum[ni][0] = 0.f; csum[ni][1] = 0.f;
            cssq[ni][0] = 0.f; cssq[ni][1] = 0.f;
        }
    }

    #pragma unroll
    for (int mi = 0; mi < 2; ++mi) {
        const int row = mBase + m0 + mi * 16 + g;
        const bool v0 = row < M, v1 = (row + 8) < M;
        #pragma unroll
        for (int ni = 0; ni < 8; ++ni) {
            const int col = n0 + ni * 8 + t2;
            float b0 = bs[col], b1 = bs[col + 1];
            float y0 = acc[mi][ni][0] + b0;
            float y1 = acc[mi][ni][1] + b1;
            float y2 = acc[mi][ni][2] + b0;
            float y3 = acc[mi][ni][3] + b1;
            if (v0)
                *reinterpret_cast<float2*>(outp + (size_t)row * outLd + nBase + col)
                    = make_float2(y0, y1);
            if (v1)
                *reinterpret_cast<float2*>(outp + (size_t)(row + 8) * outLd + nBase + col)
                    = make_float2(y2, y3);
            if (ASEL == 1) {
                if (v0) {
                    csum[ni][0] += y0; csum[ni][1] += y1;
                    cssq[ni][0] += y0 * y0; cssq[ni][1] += y1 * y1;
                }
                if (v1) {
                    csum[ni][0] += y2; csum[ni][1] += y3;
                    cssq[ni][0] += y2 * y2; cssq[ni][1] += y3 * y3;
                }
            }
        }
    }
    if (ASEL == 1) {
        #pragma unroll
        for (int ni = 0; ni < 8; ++ni)
            #pragma unroll
            for (int par = 0; par < 2; ++par) {
                float s = csum[ni][par], q = cssq[ni][par];
                #pragma unroll
                for (int o = 4; o < 32; o <<= 1) {
                    s += __shfl_xor_sync(0xFFFFFFFFu, s, o);
                    q += __shfl_xor_sync(0xFFFFFFFFu, q, o);
                }
                if (g == 0) {
                    atomicAdd(&s_sum[n0 + ni * 8 + t2 + par], s);
                    atomicAdd(&s_ssq[n0 + ni * 8 + t2 + par], q);
                }
            }
        __syncthreads();
        if (tid < 128) {
            atomicAdd(&g_sum2[nBase + tid], s_sum[tid]);
            atomicAdd(&g_ssq2[nBase + tid], s_ssq[tid]);
        }
    }
}

// ---------------- final GEMM (bf16 3-pass): out = relu(relu(bn2(Z2))@Wl+bl) --
__global__ void __launch_bounds__(256, 2)
final_gemm(float* __restrict__ outExt, int M)
{
    extern __shared__ char smem[];
    const uint32_t sb = smem_u32(smem);
    const int tid = threadIdx.x, wid = tid >> 5, lane = tid & 31;
    const int mBase = blockIdx.x * 128;

    const int m0 = (wid & 3) * 32;
    const int n0 = (wid >> 2) * 64;
    float acc[2][8][4];
    #pragma unroll
    for (int mi = 0; mi < 2; ++mi)
        #pragma unroll
        for (int ni = 0; ni < 8; ++ni)
            #pragma unroll
            for (int c = 0; c < 4; ++c) acc[mi][ni][c] = 0.f;

    const uint32_t aRowOff = (uint32_t)(m0 + (lane & 15)) * (uint32_t)A_STRIDE
                           + (uint32_t)(lane >> 4) * 16u;
    const uint32_t bOff = (uint32_t)((lane & 7) + ((lane >> 3) & 1) * 8) * 272u
                        + ((uint32_t)(lane >> 4) * 8u + (uint32_t)n0) * 2u;

    #pragma unroll 1
    for (int c = 0; c < 4; ++c) {
        if (c) __syncthreads();
        {
            uint4* dh = reinterpret_cast<uint4*>(smem + Q_WHI);
            uint4* dl = reinterpret_cast<uint4*>(smem + Q_WLO);
            const uint4* sh = g_WlH + (size_t)(c * 64) * 17;
            const uint4* sl = g_WlL + (size_t)(c * 64) * 17;
            for (int i = tid; i < 1088; i += 256) {
                int kk = i / 17, q = i - kk * 17;
                dh[i] = sh[(size_t)kk * 17 + q];
                dl[i] = sl[(size_t)kk * 17 + q];
            }
        }
        {
            const int r = tid >> 1, h = tid & 1, rg = mBase + r;
            char* ahi = smem + Q_AHI + r * A_STRIDE;
            char* alo = smem + Q_ALO + r * A_STRIDE;
            const float4* ar = reinterpret_cast<const float4*>(
                (const float*)g_Z2 + (size_t)rg * 256 + c * 64);
            #pragma unroll
            for (int jj = 0; jj < 8; ++jj) {
                int j = h * 8 + jj;
                float4 v = make_float4(0.f, 0.f, 0.f, 0.f);
                if (rg < M) {
                    v = ar[j];
                    int kg = c * 64 + j * 4;
                    float4 sc = ld4(g_scale2 + kg), sh4 = ld4(g_shift2 + kg);
                    v.x = fmaxf(fmaf(v.x, sc.x, sh4.x), 0.f);
                    v.y = fmaxf(fmaf(v.y, sc.y, sh4.y), 0.f);
                    v.z = fmaxf(fmaf(v.z, sc.z, sh4.z), 0.f);
                    v.w = fmaxf(fmaf(v.w, sc.w, sh4.w), 0.f);
                }
                split_store(ahi, alo, j, v);
            }
        }
        __syncthreads();

        #pragma unroll
        for (int kt = 0; kt < 4; ++kt) {
            const uint32_t k0b = (uint32_t)kt * 32u;
            const uint32_t kwb = (uint32_t)kt * 4352u;
            uint32_t ah[2][4], al[2][4];
            ldsm4(ah[0], sb + Q_AHI + aRowOff + k0b);
            ldsm4(ah[1], sb + Q_AHI + aRowOff + 16u * A_STRIDE + k0b);
            ldsm4(al[0], sb + Q_ALO + aRowOff + k0b);
            ldsm4(al[1], sb + Q_ALO + aRowOff + 16u * A_STRIDE + k0b);

            #pragma unroll
            for (int ni2 = 0; ni2 < 4; ++ni2) {
                uint32_t th[4], tl[4];
                ldsm4t(th, sb + Q_WHI + bOff + kwb + (uint32_t)ni2 * 32u);
                ldsm4t(tl, sb + Q_WLO + bOff + kwb + (uint32_t)ni2 * 32u);
                #pragma unroll
                for (int mi = 0; mi < 2; ++mi) {
                    mma_bf16(acc[mi][2 * ni2],     ah[mi], th);
                    mma_bf16(acc[mi][2 * ni2],     al[mi], th);
                    mma_bf16(acc[mi][2 * ni2],     ah[mi], tl);
                    mma_bf16(acc[mi][2 * ni2 + 1], ah[mi], th + 2);
                    mma_bf16(acc[mi][2 * ni2 + 1], al[mi], th + 2);
                    mma_bf16(acc[mi][2 * ni2 + 1], ah[mi], tl + 2);
                }
            }
        }
    }
    __syncthreads();

    const int g = lane >> 2, t2 = (lane & 3) * 2;
    #pragma unroll
    for (int mi = 0; mi < 2; ++mi) {
        const int row = mBase + m0 + mi * 16 + g;
        const bool v0 = row < M, v1 = (row + 8) < M;
        #pragma unroll
        for (int ni = 0; ni < 8; ++ni) {
            const int col = n0 + ni * 8 + t2;
            float bb0 = g_blv[col], bb1 = g_blv[col + 1];
            float y0 = fmaxf(acc[mi][ni][0] + bb0, 0.f);
            float y1 = fmaxf(acc[mi][ni][1] + bb1, 0.f);
            float y2 = fmaxf(acc[mi][ni][2] + bb0, 0.f);
            float y3 = fmaxf(acc[mi][ni][3] + bb1, 0.f);
            if (v0)
                *reinterpret_cast<float2*>(outExt + (size_t)row * 128 + col)
                    = make_float2(y0, y1);
            if (v1)
                *reinterpret_cast<float2*>(outExt + (size_t)(row + 8) * 128 + col)
                    = make_float2(y2, y3);
        }
    }
}

// ---------------- BN finalize -------------------------------------------------
__global__ void finalize_bn(const float* __restrict__ gamma,
                            const float* __restrict__ beta,
                            int C, float invM, int which)
{
    int i = blockIdx.x * blockDim.x + threadIdx.x;
    if (i < C) {
        const float* sum = (which == 0) ? g_sum1 : g_sum2;
        const float* ssq = (which == 0) ? g_ssq1 : g_ssq2;
        float*     scale = (which == 0) ? g_scale1 : g_scale2;
        float*     shift = (which == 0) ? g_shift1 : g_shift2;
        float mu  = sum[i] * invM;
        float var = ssq[i] * invM - mu * mu;
        float inv = rsqrtf(var + EPS_BN);
        float sc  = gamma[i] * inv;
        scale[i] = sc;
        shift[i] = beta[i] - mu * sc;
    }
}

// ---------------- BN+ReLU then scatter-add (fp16 Y, vector atomics) ----------
__global__ void scatter_kernel(const int* __restrict__ ecol) {
    const int lane   = threadIdx.x & 31;
    const int warp   = (blockIdx.x * blockDim.x + threadIdx.x) >> 5;
    const int nWarps = (gridDim.x * blockDim.x) >> 5;

    float4 sc = *reinterpret_cast<const float4*>(&g_scale1[lane << 2]);
    float4 sh = *reinterpret_cast<const float4*>(&g_shift1[lane << 2]);

    for (int e = warp; e < E_EDGES; e += nWarps) {
        int c = ecol[e];
        uint2 raw = __ldcs(reinterpret_cast<const uint2*>(&g_Y[(size_t)e * 128 + (lane << 2)]));
        __half2 ha = *reinterpret_cast<__half2*>(&raw.x);
        __half2 hb = *reinterpret_cast<__half2*>(&raw.y);
        float2 f01 = __half22float2(ha);
        float2 f23 = __half22float2(hb);
        float y0 = fmaxf(fmaf(f01.x, sc.x, sh.x), 0.f);
        float y1 = fmaxf(fmaf(f01.y, sc.y, sh.y), 0.f);
        float y2 = fmaxf(fmaf(f23.x, sc.z, sh.z), 0.f);
        float y3 = fmaxf(fmaf(f23.y, sc.w, sh.w), 0.f);
        float* dst = &g_s[(size_t)c * 128 + (lane << 2)];
        asm volatile("red.global.add.v4.f32 [%0], {%1,%2,%3,%4};"
                     :: "l"(dst), "f"(y0), "f"(y1), "f"(y2), "f"(y3)
                     : "memory");
        if (lane == 0) atomicAdd(&g_cnt[c], 1);
    }
}

// ---------------- launch ------------------------------------------------------
extern "C" void kernel_launch(void* const* d_in, const int* in_sizes, int n_in,
                              void* d_out, int out_size)
{
    const float* x     = (const float*)d_in[0];
    const int*   eidx  = (const int*)  d_in[1];
    const float* eattr = (const float*)d_in[2];
    const float* W1  = (const float*)d_in[5];
    const float* b1  = (const float*)d_in[6];
    const float* g1  = (const float*)d_in[7];
    const float* be1 = (const float*)d_in[8];
    const float* W2  = (const float*)d_in[9];
    const float* b2  = (const float*)d_in[10];
    const float* g2  = (const float*)d_in[11];
    const float* be2 = (const float*)d_in[12];
    const float* Wl  = (const float*)d_in[13];
    const float* bl  = (const float*)d_in[14];
    float* out = (float*)d_out;

    const int* erow = eidx;
    const int* ecol = eidx + E_EDGES;

    cudaFuncSetAttribute(gemm1_mma, cudaFuncAttributeMaxDynamicSharedMemorySize, G3_TOT);
    cudaFuncSetAttribute(mma16_gemm<2, 0>, cudaFuncAttributeMaxDynamicSharedMemorySize, M_TOT);
    cudaFuncSetAttribute(mma16_gemm<4, 1>, cudaFuncAttributeMaxDynamicSharedMemorySize, M_TOT);
    cudaFuncSetAttribute(final_gemm, cudaFuncAttributeMaxDynamicSharedMemorySize, Q_TOT);

    const int MB = (N_NODES + 127) / 128;   // 391

    // 0) zero accumulators + prep weight images (+ final bias)
    zero_kernel<<<2048, 256>>>();
    prep_W<<<480, 256>>>(W1, W2, Wl, bl);

    // 1) P = x @ W1_top + b1 (fp16 single-pass)
    mma16_gemm<2, 0><<<dim3(MB, 1), 256, M_TOT>>>(x, N_NODES, b1);

    // 2) persistent fp16 1-pass: Y = eattr @ W1_bot + P[row]; fused BN1 stats
    gemm1_mma<<<G_GRID, 256, G3_TOT>>>(eattr, erow);

    // 3) BN1 scale/shift
    finalize_bn<<<1, 256>>>(g1, be1, 128, 1.f / (float)E_EDGES, 0);

    // 4) BN1 + ReLU + scatter (fp16 Y)
    scatter_kernel<<<2368, 256>>>(ecol);

    // 5) Z2 = concat(x, s/cnt) @ W2 + b2, fused h2in build + BN2 stats
    mma16_gemm<4, 1><<<dim3(MB, 2), 256, M_TOT>>>(x, N_NODES, b2);

    // 6) BN2 scale/shift
    finalize_bn<<<1, 256>>>(g2, be2, 256, 1.f / (float)N_NODES, 1);

    // 7) out = relu(relu(bn2(Z2)) @ Wl + bl)  (bf16 3-pass, Wl near-exact)
    final_gemm<<<dim3(MB, 1), 256, Q_TOT>>>(out, N_NODES);
}

// round 16
// speedup vs baseline: 1.5448x; 1.0906x over previous
#include <cuda_runtime.h>
#include <cuda_bf16.h>
#include <cuda_fp16.h>
#include <cstdint>

#define E_EDGES 1600000
#define N_NODES 50000
#define EPS_BN 1e-5f

// ---------------- scratch (device globals; no allocations allowed) ----------
__device__ __half g_Y[(size_t)E_EDGES * 128];     // pre-BN edge activations (fp16)
__device__ float g_P[(size_t)N_NODES * 128];      // x @ W1_top + b1
__device__ __half g_s[(size_t)N_NODES * 128];     // scatter-sum accumulator (fp16)
__device__ int   g_cnt[N_NODES];
__device__ float g_Z2[(size_t)N_NODES * 256];
__device__ float g_sum1[128], g_ssq1[128], g_scale1[128], g_shift1[128];
__device__ float g_sum2[256], g_ssq2[256], g_scale2[256], g_shift2[256];
__device__ float g_blv[128];                       // final-layer bias
// Weight images (padded rows, uint4-clean)
__device__ uint4 g_W1bH16[1088];                   // W1_bot fp16 [64 k][136 n]
__device__ uint4 g_W1tH16[2176];                   // W1_top fp16 [128 k][136 n]
__device__ uint4 g_W2H16[8448];                    // W2 fp16 [256 k][264 n]
__device__ uint4 g_WlH[4352],  g_WlL[4352];        // Wl bf16 hi/lo [256 k][136 n]

__device__ __forceinline__ float4 ld4(const float* p) {
    return *reinterpret_cast<const float4*>(p);
}
__device__ __forceinline__ uint32_t smem_u32(const void* p) {
    uint32_t a;
    asm("{ .reg .u64 t; cvta.to.shared.u64 t, %1; cvt.u32.u64 %0, t; }" : "=r"(a) : "l"(p));
    return a;
}

// ---------------- warp MMA primitives (sm_80 baseline) ----------------------
__device__ __forceinline__ void mma_bf16(float* c, const uint32_t* a, const uint32_t* b) {
    asm volatile(
        "mma.sync.aligned.m16n8k16.row.col.f32.bf16.bf16.f32 "
        "{%0,%1,%2,%3}, {%4,%5,%6,%7}, {%8,%9}, {%0,%1,%2,%3};"
        : "+f"(c[0]), "+f"(c[1]), "+f"(c[2]), "+f"(c[3])
        : "r"(a[0]), "r"(a[1]), "r"(a[2]), "r"(a[3]), "r"(b[0]), "r"(b[1]));
}
__device__ __forceinline__ void mma_f16(float* c, const uint32_t* a, const uint32_t* b) {
    asm volatile(
        "mma.sync.aligned.m16n8k16.row.col.f32.f16.f16.f32 "
        "{%0,%1,%2,%3}, {%4,%5,%6,%7}, {%8,%9}, {%0,%1,%2,%3};"
        : "+f"(c[0]), "+f"(c[1]), "+f"(c[2]), "+f"(c[3])
        : "r"(a[0]), "r"(a[1]), "r"(a[2]), "r"(a[3]), "r"(b[0]), "r"(b[1]));
}
__device__ __forceinline__ void ldsm4(uint32_t* r, uint32_t addr) {
    asm volatile("ldmatrix.sync.aligned.m8n8.x4.shared.b16 {%0,%1,%2,%3}, [%4];"
        : "=r"(r[0]), "=r"(r[1]), "=r"(r[2]), "=r"(r[3]) : "r"(addr));
}
__device__ __forceinline__ void ldsm4t(uint32_t* r, uint32_t addr) {
    asm volatile("ldmatrix.sync.aligned.m8n8.x4.trans.shared.b16 {%0,%1,%2,%3}, [%4];"
        : "=r"(r[0]), "=r"(r[1]), "=r"(r[2]), "=r"(r[3]) : "r"(addr));
}
__device__ __forceinline__ void split_store(char* hi, char* lo, int j, float4 v) {
    __nv_bfloat16 h0 = __float2bfloat16_rn(v.x), h1 = __float2bfloat16_rn(v.y);
    __nv_bfloat16 h2 = __float2bfloat16_rn(v.z), h3 = __float2bfloat16_rn(v.w);
    __nv_bfloat162 hp0(h0, h1), hp1(h2, h3);
    __nv_bfloat162 lp0(__float2bfloat16_rn(v.x - __bfloat162float(h0)),
                       __float2bfloat16_rn(v.y - __bfloat162float(h1)));
    __nv_bfloat162 lp1(__float2bfloat16_rn(v.z - __bfloat162float(h2)),
                       __float2bfloat16_rn(v.w - __bfloat162float(h3)));
    *reinterpret_cast<uint2*>(hi + j * 8) =
        make_uint2(*reinterpret_cast<uint32_t*>(&hp0), *reinterpret_cast<uint32_t*>(&hp1));
    *reinterpret_cast<uint2*>(lo + j * 8) =
        make_uint2(*reinterpret_cast<uint32_t*>(&lp0), *reinterpret_cast<uint32_t*>(&lp1));
}
__device__ __forceinline__ void pack_f16_store(char* ai, int j, float4 v0, float4 v1) {
    __half2 a = __floats2half2_rn(v0.x, v0.y);
    __half2 b = __floats2half2_rn(v0.z, v0.w);
    __half2 c = __floats2half2_rn(v1.x, v1.y);
    __half2 d = __floats2half2_rn(v1.z, v1.w);
    *reinterpret_cast<uint4*>(ai + j * 8) =
        make_uint4(*reinterpret_cast<uint32_t*>(&a), *reinterpret_cast<uint32_t*>(&b),
                   *reinterpret_cast<uint32_t*>(&c), *reinterpret_cast<uint32_t*>(&d));
}
__device__ __forceinline__ void cp_async16(uint32_t saddr, const void* gptr) {
    asm volatile("cp.async.cg.shared.global [%0], [%1], 16;"
                 :: "r"(saddr), "l"(gptr) : "memory");
}
__device__ __forceinline__ void prefetchL1(const void* gptr) {
    asm volatile("prefetch.global.L1 [%0];" :: "l"(gptr));
}

// ---------------- zero scratch ----------------------------------------------
__global__ void zero_kernel() {
    int idx = blockIdx.x * blockDim.x + threadIdx.x;
    int stride = gridDim.x * blockDim.x;
    uint4 z4 = make_uint4(0u, 0u, 0u, 0u);
    const int total4 = N_NODES * 16;   // g_s halves as uint4 (8 halves each)
    uint4* s4 = reinterpret_cast<uint4*>(g_s);
    for (int i = idx; i < total4; i += stride) s4[i] = z4;
    for (int i = idx; i < N_NODES; i += stride) g_cnt[i] = 0;
    if (idx < 128) { g_sum1[idx] = 0.f; g_ssq1[idx] = 0.f; }
    if (idx < 256) { g_sum2[idx] = 0.f; g_ssq2[idx] = 0.f; }
}

// ---------------- prep: all weight images + final bias ------------------------
__global__ void prep_W(const float* __restrict__ W1, const float* __restrict__ W2,
                       const float* __restrict__ Wl, const float* __restrict__ bl) {
    int idx = blockIdx.x * blockDim.x + threadIdx.x;
    if (idx < 8192) {                       // W1_bot fp16: [64 k][128 n] -> 136
        int k = idx >> 7, n = idx & 127;
        __half h = __float2half_rn(W1[(size_t)(128 + k) * 128 + n]);
        reinterpret_cast<uint16_t*>(g_W1bH16)[k * 136 + n] = *reinterpret_cast<uint16_t*>(&h);
        if (idx < 128) g_blv[idx] = bl[idx];
    } else if (idx < 24576) {               // W1_top fp16: [128 k][128 n] -> 136
        int l = idx - 8192, k = l >> 7, n = l & 127;
        __half h = __float2half_rn(W1[(size_t)k * 128 + n]);
        reinterpret_cast<uint16_t*>(g_W1tH16)[k * 136 + n] = *reinterpret_cast<uint16_t*>(&h);
    } else if (idx < 90112) {               // W2 fp16: [256 k][256 n] -> 264
        int l = idx - 24576, k = l >> 8, n = l & 255;
        __half h = __float2half_rn(W2[(size_t)k * 256 + n]);
        reinterpret_cast<uint16_t*>(g_W2H16)[k * 264 + n] = *reinterpret_cast<uint16_t*>(&h);
    } else if (idx < 122880) {              // Wl bf16 hi/lo: [256 k][128 n] -> 136
        int l = idx - 90112, k = l >> 7, n = l & 127;
        float f = Wl[(size_t)k * 128 + n];
        __nv_bfloat16 h = __float2bfloat16_rn(f);
        __nv_bfloat16 lo = __float2bfloat16_rn(f - __bfloat162float(h));
        reinterpret_cast<uint16_t*>(g_WlH)[k * 136 + n] = *reinterpret_cast<uint16_t*>(&h);
        reinterpret_cast<uint16_t*>(g_WlL)[k * 136 + n] = *reinterpret_cast<uint16_t*>(&lo);
    }
}

// ---------------- SMEM layouts ------------------------------------------------
#define A_STRIDE 144
// final bf16 3-pass GEMM:
#define Q_AHI 0
#define Q_ALO 18432
#define Q_WHI 36864
#define Q_WLO 54272
#define Q_TOT 73216
// fp16 single-pass node GEMM:
#define M_A 0
#define M_W 18432
#define M_BIAS 35840
#define M_SUM 36352
#define M_SSQ 36864
#define M_TOT 37376
// gemm1 (fp16 single-pass, persistent, 2 CTAs/SM):
#define G3_A 0
#define G3_W 18432
#define G3_STAGE 35840
#define G3_SROWSTG 70656
#define G3_SROW 71168
#define G3_SUM 71680
#define G3_SSQ 72192
#define G3_TOT 72704
#define G_GRID 296
#define G_NT (E_EDGES / 128)

// ---------------- gemm1 (persistent, fp16 1-pass): Y = eattr@W1_bot + P[row] --
__global__ void __launch_bounds__(256, 2)
gemm1_mma(const float* __restrict__ eattr, const int* __restrict__ erow) {
    extern __shared__ char smem[];
    const uint32_t sb = smem_u32(smem);
    const int tid = threadIdx.x, wid = tid >> 5, lane = tid & 31;

    {
        uint4* dw = reinterpret_cast<uint4*>(smem + G3_W);
        for (int i = tid; i < 1088; i += 256) dw[i] = g_W1bH16[i];
    }
    if (tid < 128) {
        ((float*)(smem + G3_SUM))[tid] = 0.f;
        ((float*)(smem + G3_SSQ))[tid] = 0.f;
    }

    {
        int t0 = blockIdx.x;
        const char* src = (const char*)(eattr + (size_t)t0 * 128 * 64);
        #pragma unroll
        for (int i = tid; i < 2048; i += 256) {
            int r = i >> 4, q = i & 15;
            cp_async16(sb + G3_STAGE + r * 272 + q * 16, src + (size_t)r * 256 + q * 16);
        }
        if (tid < 32)
            cp_async16(sb + G3_SROWSTG + tid * 16,
                       (const char*)(erow + (size_t)t0 * 128) + tid * 16);
        asm volatile("cp.async.commit_group;" ::: "memory");
    }

    const int m0 = (wid & 3) * 32;
    const int n0 = (wid >> 2) * 64;
    const uint32_t aRowOff = (uint32_t)(m0 + (lane & 15)) * (uint32_t)A_STRIDE
                           + (uint32_t)(lane >> 4) * 16u;
    const uint32_t bOff = (uint32_t)((lane & 7) + ((lane >> 3) & 1) * 8) * 272u
                        + ((uint32_t)(lane >> 4) * 8u + (uint32_t)n0) * 2u;
    const int g = lane >> 2, t2 = (lane & 3) * 2;
    const int* s_row = (const int*)(smem + G3_SROW);
    float* s_sum = (float*)(smem + G3_SUM);
    float* s_ssq = (float*)(smem + G3_SSQ);

    float csum[8][2], cssq[8][2];
    #pragma unroll
    for (int ni = 0; ni < 8; ++ni) {
        csum[ni][0] = 0.f; csum[ni][1] = 0.f;
        cssq[ni][0] = 0.f; cssq[ni][1] = 0.f;
    }

    for (int t = blockIdx.x; t < G_NT; t += G_GRID) {
        asm volatile("cp.async.wait_group 0;" ::: "memory");
        __syncthreads();

        {
            const int r = tid >> 1, h = tid & 1;
            const char* srow = smem + G3_STAGE + r * 272;
            char* ai = smem + G3_A + r * A_STRIDE;
            #pragma unroll
            for (int p = 0; p < 4; ++p) {
                int j = h * 8 + p * 2;
                float4 v0 = *reinterpret_cast<const float4*>(srow + j * 16);
                float4 v1 = *reinterpret_cast<const float4*>(srow + j * 16 + 16);
                pack_f16_store(ai, j, v0, v1);
            }
            if (tid < 128)
                ((int*)(smem + G3_SROW))[tid] = ((const int*)(smem + G3_SROWSTG))[tid];
        }
        __syncthreads();

        int G00 = s_row[m0 + g],      G01 = s_row[m0 + g + 8];
        int G10 = s_row[m0 + 16 + g], G11 = s_row[m0 + 16 + g + 8];
        {
            const float* pb = g_P;
            prefetchL1(pb + (size_t)G00 * 128 + n0 + t2);
            prefetchL1(pb + (size_t)G00 * 128 + n0 + t2 + 32);
            prefetchL1(pb + (size_t)G01 * 128 + n0 + t2);
            prefetchL1(pb + (size_t)G01 * 128 + n0 + t2 + 32);
            prefetchL1(pb + (size_t)G10 * 128 + n0 + t2);
            prefetchL1(pb + (size_t)G10 * 128 + n0 + t2 + 32);
            prefetchL1(pb + (size_t)G11 * 128 + n0 + t2);
            prefetchL1(pb + (size_t)G11 * 128 + n0 + t2 + 32);
        }

        if (t + G_GRID < G_NT) {
            int tn = t + G_GRID;
            const char* src = (const char*)(eattr + (size_t)tn * 128 * 64);
            #pragma unroll
            for (int i = tid; i < 2048; i += 256) {
                int r = i >> 4, q = i & 15;
                cp_async16(sb + G3_STAGE + r * 272 + q * 16, src + (size_t)r * 256 + q * 16);
            }
            if (tid < 32)
                cp_async16(sb + G3_SROWSTG + tid * 16,
                           (const char*)(erow + (size_t)tn * 128) + tid * 16);
        }
        asm volatile("cp.async.commit_group;" ::: "memory");

        float acc[2][8][4];
        #pragma unroll
        for (int mi = 0; mi < 2; ++mi)
            #pragma unroll
            for (int ni = 0; ni < 8; ++ni)
                #pragma unroll
                for (int c = 0; c < 4; ++c) acc[mi][ni][c] = 0.f;

        #pragma unroll
        for (int kt = 0; kt < 4; ++kt) {
            const uint32_t k0b = (uint32_t)kt * 32u;
            const uint32_t kwb = (uint32_t)kt * 4352u;
            uint32_t a0[4], a1[4];
            ldsm4(a0, sb + G3_A + aRowOff + k0b);
            ldsm4(a1, sb + G3_A + aRowOff + 16u * A_STRIDE + k0b);

            #pragma unroll
            for (int ni2 = 0; ni2 < 4; ++ni2) {
                uint32_t th[4];
                ldsm4t(th, sb + G3_W + bOff + kwb + (uint32_t)ni2 * 32u);
                mma_f16(acc[0][2 * ni2],     a0, th);
                mma_f16(acc[0][2 * ni2 + 1], a0, th + 2);
                mma_f16(acc[1][2 * ni2],     a1, th);
                mma_f16(acc[1][2 * ni2 + 1], a1, th + 2);
            }
        }

        const int mBase = t * 128;
        #pragma unroll
        for (int mi = 0; mi < 2; ++mi) {
            const int r0 = m0 + mi * 16 + g;
            const int G0 = (mi == 0) ? G00 : G10;
            const int G1 = (mi == 0) ? G01 : G11;
            const int row = mBase + r0;
            #pragma unroll
            for (int ni = 0; ni < 8; ++ni) {
                const int col = n0 + ni * 8 + t2;
                float2 p0 = *reinterpret_cast<const float2*>(g_P + (size_t)G0 * 128 + col);
                float2 p1 = *reinterpret_cast<const float2*>(g_P + (size_t)G1 * 128 + col);
                float y0 = acc[mi][ni][0] + p0.x;
                float y1 = acc[mi][ni][1] + p0.y;
                float y2 = acc[mi][ni][2] + p1.x;
                float y3 = acc[mi][ni][3] + p1.y;
                __half2 h01 = __floats2half2_rn(y0, y1);
                __half2 h23 = __floats2half2_rn(y2, y3);
                __stcs(reinterpret_cast<__half2*>(g_Y + (size_t)row * 128 + col), h01);
                __stcs(reinterpret_cast<__half2*>(g_Y + (size_t)(row + 8) * 128 + col), h23);
                csum[ni][0] += y0 + y2;
                csum[ni][1] += y1 + y3;
                cssq[ni][0] += y0 * y0 + y2 * y2;
                cssq[ni][1] += y1 * y1 + y3 * y3;
            }
        }
    }

    #pragma unroll
    for (int ni = 0; ni < 8; ++ni)
        #pragma unroll
        for (int par = 0; par < 2; ++par) {
            float s = csum[ni][par], q = cssq[ni][par];
            #pragma unroll
            for (int o = 4; o < 32; o <<= 1) {
                s += __shfl_xor_sync(0xFFFFFFFFu, s, o);
                q += __shfl_xor_sync(0xFFFFFFFFu, q, o);
            }
            if (g == 0) {
                atomicAdd(&s_sum[n0 + ni * 8 + t2 + par], s);
                atomicAdd(&s_ssq[n0 + ni * 8 + t2 + par], q);
            }
        }
    __syncthreads();
    if (tid < 128) {
        atomicAdd(&g_sum1[tid], s_sum[tid]);
        atomicAdd(&g_ssq1[tid], s_ssq[tid]);
    }
}

// ---------------- fp16 single-pass node GEMM ---------------------------------
// ASEL 0: A = x [M,128] (KCH=2), out = g_P (+bias)
// ASEL 1: A = concat(x, g_s/cnt) [M,256] (KCH=4), out = g_Z2 (+bias, BN2 stats)
template<int KCH, int ASEL>
__global__ void __launch_bounds__(256, 2)
mma16_gemm(const float* __restrict__ x, int M, const float* __restrict__ bias)
{
    extern __shared__ char smem[];
    const uint32_t sb = smem_u32(smem);
    const int tid = threadIdx.x, wid = tid >> 5, lane = tid & 31;
    const int mBase = blockIdx.x * 128;
    const int nBase = blockIdx.y * 128;

    const uint4* WH = (ASEL == 0) ? g_W1tH16 : g_W2H16;
    const int WR16 = (ASEL == 0) ? 17 : 33;
    float* outp = (ASEL == 0) ? (float*)g_P : (float*)g_Z2;
    const int outLd = (ASEL == 0) ? 128 : 256;

    if (tid < 128) {
        ((float*)(smem + M_BIAS))[tid] = bias[nBase + tid];
        ((float*)(smem + M_SUM))[tid] = 0.f;
        ((float*)(smem + M_SSQ))[tid] = 0.f;
    }

    const int m0 = (wid & 3) * 32;
    const int n0 = (wid >> 2) * 64;
    float acc[2][8][4];
    #pragma unroll
    for (int mi = 0; mi < 2; ++mi)
        #pragma unroll
        for (int ni = 0; ni < 8; ++ni)
            #pragma unroll
            for (int c = 0; c < 4; ++c) acc[mi][ni][c] = 0.f;

    const uint32_t aRowOff = (uint32_t)(m0 + (lane & 15)) * (uint32_t)A_STRIDE
                           + (uint32_t)(lane >> 4) * 16u;
    const uint32_t bOff = (uint32_t)((lane & 7) + ((lane >> 3) & 1) * 8) * 272u
                        + ((uint32_t)(lane >> 4) * 8u + (uint32_t)n0) * 2u;

    #pragma unroll 1
    for (int c = 0; c < KCH; ++c) {
        if (c) __syncthreads();
        {
            uint4* dw = reinterpret_cast<uint4*>(smem + M_W);
            const uint4* sh = WH + (size_t)(c * 64) * WR16 + (nBase >> 3);
            for (int i = tid; i < 1088; i += 256) {
                int kk = i / 17, q = i - kk * 17;
                dw[i] = sh[(size_t)kk * WR16 + q];
            }
        }
        {
            const int r = tid >> 1, h = tid & 1, rg = mBase + r;
            char* ai = smem + M_A + r * A_STRIDE;
            if (ASEL == 1 && c >= 2) {
                float invc = 0.f;
                const __half* hbase = (const __half*)g_s + (size_t)rg * 128 + (c - 2) * 64;
                if (rg < M) {
                    int ct = g_cnt[rg];
                    invc = (ct > 0) ? (1.f / (float)ct) : 0.f;
                }
                #pragma unroll
                for (int p = 0; p < 4; ++p) {
                    int j = h * 8 + p * 2;
                    float4 v0 = make_float4(0.f, 0.f, 0.f, 0.f);
                    float4 v1 = make_float4(0.f, 0.f, 0.f, 0.f);
                    if (rg < M) {
                        uint2 ra = *reinterpret_cast<const uint2*>(hbase + j * 4);
                        uint2 rb = *reinterpret_cast<const uint2*>(hbase + j * 4 + 4);
                        float2 f0 = __half22float2(*reinterpret_cast<__half2*>(&ra.x));
                        float2 f1 = __half22float2(*reinterpret_cast<__half2*>(&ra.y));
                        float2 f2 = __half22float2(*reinterpret_cast<__half2*>(&rb.x));
                        float2 f3 = __half22float2(*reinterpret_cast<__half2*>(&rb.y));
                        v0 = make_float4(f0.x * invc, f0.y * invc, f1.x * invc, f1.y * invc);
                        v1 = make_float4(f2.x * invc, f2.y * invc, f3.x * invc, f3.y * invc);
                    }
                    pack_f16_store(ai, j, v0, v1);
                }
            } else {
                const float* base = x + (size_t)rg * 128 + c * 64;
                #pragma unroll
                for (int p = 0; p < 4; ++p) {
                    int j = h * 8 + p * 2;
                    float4 v0 = make_float4(0.f, 0.f, 0.f, 0.f);
                    float4 v1 = make_float4(0.f, 0.f, 0.f, 0.f);
                    if (rg < M) {
                        v0 = ld4(base + j * 4);
                        v1 = ld4(base + j * 4 + 4);
                    }
                    pack_f16_store(ai, j, v0, v1);
                }
            }
        }
        __syncthreads();

        #pragma unroll
        for (int kt = 0; kt < 4; ++kt) {
            const uint32_t k0b = (uint32_t)kt * 32u;
            const uint32_t kwb = (uint32_t)kt * 4352u;
            uint32_t a0[4], a1[4];
            ldsm4(a0, sb + M_A + aRowOff + k0b);
            ldsm4(a1, sb + M_A + aRowOff + 16u * A_STRIDE + k0b);
            #pragma unroll
            for (int ni2 = 0; ni2 < 4; ++ni2) {
                uint32_t th[4];
                ldsm4t(th, sb + M_W + bOff + kwb + (uint32_t)ni2 * 32u);
                mma_f16(acc[0][2 * ni2],     a0, th);
                mma_f16(acc[0][2 * ni2 + 1], a0, th + 2);
                mma_f16(acc[1][2 * ni2],     a1, th);
                mma_f16(acc[1][2 * ni2 + 1], a1, th + 2);
            }
        }
    }
    __syncthreads();

    const float* bs = (const float*)(smem + M_BIAS);
    float* s_sum = (float*)(smem + M_SUM);
    float* s_ssq = (float*)(smem + M_SSQ);
    const int g = lane >> 2, t2 = (lane & 3) * 2;

    float csum[8][2], cssq[8][2];
    if (ASEL == 1) {
        #pragma unroll
        for (int ni = 0; ni < 8; ++ni) {
            csum[ni][0] = 0.f; csum[ni][1] = 0.f;
            cssq[ni][0] = 0.f; cssq[ni][1] = 0.f;
        }
    }

    #pragma unroll
    for (int mi = 0; mi < 2; ++mi) {
        const int row = mBase + m0 + mi * 16 + g;
        const bool v0 = row < M, v1 = (row + 8) < M;
        #pragma unroll
        for (int ni = 0; ni < 8; ++ni) {
            const int col = n0 + ni * 8 + t2;
            float b0 = bs[col], b1 = bs[col + 1];
            float y0 = acc[mi][ni][0] + b0;
            float y1 = acc[mi][ni][1] + b1;
            float y2 = acc[mi][ni][2] + b0;
            float y3 = acc[mi][ni][3] + b1;
            if (v0)
                *reinterpret_cast<float2*>(outp + (size_t)row * outLd + nBase + col)
                    = make_float2(y0, y1);
            if (v1)
                *reinterpret_cast<float2*>(outp + (size_t)(row + 8) * outLd + nBase + col)
                    = make_float2(y2, y3);
            if (ASEL == 1) {
                if (v0) {
                    csum[ni][0] += y0; csum[ni][1] += y1;
                    cssq[ni][0] += y0 * y0; cssq[ni][1] += y1 * y1;
                }
                if (v1) {
                    csum[ni][0] += y2; csum[ni][1] += y3;
                    cssq[ni][0] += y2 * y2; cssq[ni][1] += y3 * y3;
                }
            }
        }
    }
    if (ASEL == 1) {
        #pragma unroll
        for (int ni = 0; ni < 8; ++ni)
            #pragma unroll
            for (int par = 0; par < 2; ++par) {
                float s = csum[ni][par], q = cssq[ni][par];
                #pragma unroll
                for (int o = 4; o < 32; o <<= 1) {
                    s += __shfl_xor_sync(0xFFFFFFFFu, s, o);
                    q += __shfl_xor_sync(0xFFFFFFFFu, q, o);
                }
                if (g == 0) {
                    atomicAdd(&s_sum[n0 + ni * 8 + t2 + par], s);
                    atomicAdd(&s_ssq[n0 + ni * 8 + t2 + par], q);
                }
            }
        __syncthreads();
        if (tid < 128) {
            atomicAdd(&g_sum2[nBase + tid], s_sum[tid]);
            atomicAdd(&g_ssq2[nBase + tid], s_ssq[tid]);
        }
    }
}

// ---------------- final GEMM (bf16 3-pass): out = relu(relu(bn2(Z2))@Wl+bl) --
__global__ void __launch_bounds__(256, 2)
final_gemm(float* __restrict__ outExt, int M)
{
    extern __shared__ char smem[];
    const uint32_t sb = smem_u32(smem);
    const int tid = threadIdx.x, wid = tid >> 5, lane = tid & 31;
    const int mBase = blockIdx.x * 128;

    const int m0 = (wid & 3) * 32;
    const int n0 = (wid >> 2) * 64;
    float acc[2][8][4];
    #pragma unroll
    for (int mi = 0; mi < 2; ++mi)
        #pragma unroll
        for (int ni = 0; ni < 8; ++ni)
            #pragma unroll
            for (int c = 0; c < 4; ++c) acc[mi][ni][c] = 0.f;

    const uint32_t aRowOff = (uint32_t)(m0 + (lane & 15)) * (uint32_t)A_STRIDE
                           + (uint32_t)(lane >> 4) * 16u;
    const uint32_t bOff = (uint32_t)((lane & 7) + ((lane >> 3) & 1) * 8) * 272u
                        + ((uint32_t)(lane >> 4) * 8u + (uint32_t)n0) * 2u;

    #pragma unroll 1
    for (int c = 0; c < 4; ++c) {
        if (c) __syncthreads();
        {
            uint4* dh = reinterpret_cast<uint4*>(smem + Q_WHI);
            uint4* dl = reinterpret_cast<uint4*>(smem + Q_WLO);
            const uint4* sh = g_WlH + (size_t)(c * 64) * 17;
            const uint4* sl = g_WlL + (size_t)(c * 64) * 17;
            for (int i = tid; i < 1088; i += 256) {
                int kk = i / 17, q = i - kk * 17;
                dh[i] = sh[(size_t)kk * 17 + q];
                dl[i] = sl[(size_t)kk * 17 + q];
            }
        }
        {
            const int r = tid >> 1, h = tid & 1, rg = mBase + r;
            char* ahi = smem + Q_AHI + r * A_STRIDE;
            char* alo = smem + Q_ALO + r * A_STRIDE;
            const float4* ar = reinterpret_cast<const float4*>(
                (const float*)g_Z2 + (size_t)rg * 256 + c * 64);
            #pragma unroll
            for (int jj = 0; jj < 8; ++jj) {
                int j = h * 8 + jj;
                float4 v = make_float4(0.f, 0.f, 0.f, 0.f);
                if (rg < M) {
                    v = ar[j];
                    int kg = c * 64 + j * 4;
                    float4 sc = ld4(g_scale2 + kg), sh4 = ld4(g_shift2 + kg);
                    v.x = fmaxf(fmaf(v.x, sc.x, sh4.x), 0.f);
                    v.y = fmaxf(fmaf(v.y, sc.y, sh4.y), 0.f);
                    v.z = fmaxf(fmaf(v.z, sc.z, sh4.z), 0.f);
                    v.w = fmaxf(fmaf(v.w, sc.w, sh4.w), 0.f);
                }
                split_store(ahi, alo, j, v);
            }
        }
        __syncthreads();

        #pragma unroll
        for (int kt = 0; kt < 4; ++kt) {
            const uint32_t k0b = (uint32_t)kt * 32u;
            const uint32_t kwb = (uint32_t)kt * 4352u;
            uint32_t ah[2][4], al[2][4];
            ldsm4(ah[0], sb + Q_AHI + aRowOff + k0b);
            ldsm4(ah[1], sb + Q_AHI + aRowOff + 16u * A_STRIDE + k0b);
            ldsm4(al[0], sb + Q_ALO + aRowOff + k0b);
            ldsm4(al[1], sb + Q_ALO + aRowOff + 16u * A_STRIDE + k0b);

            #pragma unroll
            for (int ni2 = 0; ni2 < 4; ++ni2) {
                uint32_t th[4], tl[4];
                ldsm4t(th, sb + Q_WHI + bOff + kwb + (uint32_t)ni2 * 32u);
                ldsm4t(tl, sb + Q_WLO + bOff + kwb + (uint32_t)ni2 * 32u);
                #pragma unroll
                for (int mi = 0; mi < 2; ++mi) {
                    mma_bf16(acc[mi][2 * ni2],     ah[mi], th);
                    mma_bf16(acc[mi][2 * ni2],     al[mi], th);
                    mma_bf16(acc[mi][2 * ni2],     ah[mi], tl);
                    mma_bf16(acc[mi][2 * ni2 + 1], ah[mi], th + 2);
                    mma_bf16(acc[mi][2 * ni2 + 1], al[mi], th + 2);
                    mma_bf16(acc[mi][2 * ni2 + 1], ah[mi], tl + 2);
                }
            }
        }
    }
    __syncthreads();

    const int g = lane >> 2, t2 = (lane & 3) * 2;
    #pragma unroll
    for (int mi = 0; mi < 2; ++mi) {
        const int row = mBase + m0 + mi * 16 + g;
        const bool v0 = row < M, v1 = (row + 8) < M;
        #pragma unroll
        for (int ni = 0; ni < 8; ++ni) {
            const int col = n0 + ni * 8 + t2;
            float bb0 = g_blv[col], bb1 = g_blv[col + 1];
            float y0 = fmaxf(acc[mi][ni][0] + bb0, 0.f);
            float y1 = fmaxf(acc[mi][ni][1] + bb1, 0.f);
            float y2 = fmaxf(acc[mi][ni][2] + bb0, 0.f);
            float y3 = fmaxf(acc[mi][ni][3] + bb1, 0.f);
            if (v0)
                *reinterpret_cast<float2*>(outExt + (size_t)row * 128 + col)
                    = make_float2(y0, y1);
            if (v1)
                *reinterpret_cast<float2*>(outExt + (size_t)(row + 8) * 128 + col)
                    = make_float2(y2, y3);
        }
    }
}

// ---------------- BN finalize -------------------------------------------------
__global__ void finalize_bn(const float* __restrict__ gamma,
                            const float* __restrict__ beta,
                            int C, float invM, int which)
{
    int i = blockIdx.x * blockDim.x + threadIdx.x;
    if (i < C) {
        const float* sum = (which == 0) ? g_sum1 : g_sum2;
        const float* ssq = (which == 0) ? g_ssq1 : g_ssq2;
        float*     scale = (which == 0) ? g_scale1 : g_scale2;
        float*     shift = (which == 0) ? g_shift1 : g_shift2;
        float mu  = sum[i] * invM;
        float var = ssq[i] * invM - mu * mu;
        float inv = rsqrtf(var + EPS_BN);
        float sc  = gamma[i] * inv;
        scale[i] = sc;
        shift[i] = beta[i] - mu * sc;
    }
}

// ---------------- BN+ReLU then scatter-add (fp16 Y, fp16x2 vector atomics) ---
// 16 lanes per edge, 8 cols per lane; one red.v4.f16x2 (8 halves) per lane.
__global__ void scatter_kernel(const int* __restrict__ ecol) {
    const int lane   = threadIdx.x & 31;
    const int warp   = (blockIdx.x * blockDim.x + threadIdx.x) >> 5;
    const int nWarps = (gridDim.x * blockDim.x) >> 5;
    const int sub    = lane >> 4;           // 0 or 1: which edge of the pair
    const int c8     = (lane & 15) << 3;    // col base (8 cols)

    float4 scA = *reinterpret_cast<const float4*>(&g_scale1[c8]);
    float4 scB = *reinterpret_cast<const float4*>(&g_scale1[c8 + 4]);
    float4 shA = *reinterpret_cast<const float4*>(&g_shift1[c8]);
    float4 shB = *reinterpret_cast<const float4*>(&g_shift1[c8 + 4]);

    for (int e2 = warp * 2; e2 < E_EDGES; e2 += nWarps * 2) {
        int e = e2 + sub;
        int c = ecol[e];
        uint4 raw = __ldcs(reinterpret_cast<const uint4*>(&g_Y[(size_t)e * 128 + c8]));
        float2 f0 = __half22float2(*reinterpret_cast<__half2*>(&raw.x));
        float2 f1 = __half22float2(*reinterpret_cast<__half2*>(&raw.y));
        float2 f2 = __half22float2(*reinterpret_cast<__half2*>(&raw.z));
        float2 f3 = __half22float2(*reinterpret_cast<__half2*>(&raw.w));
        float y0 = fmaxf(fmaf(f0.x, scA.x, shA.x), 0.f);
        float y1 = fmaxf(fmaf(f0.y, scA.y, shA.y), 0.f);
        float y2 = fmaxf(fmaf(f1.x, scA.z, shA.z), 0.f);
        float y3 = fmaxf(fmaf(f1.y, scA.w, shA.w), 0.f);
        float y4 = fmaxf(fmaf(f2.x, scB.x, shB.x), 0.f);
        float y5 = fmaxf(fmaf(f2.y, scB.y, shB.y), 0.f);
        float y6 = fmaxf(fmaf(f3.x, scB.z, shB.z), 0.f);
        float y7 = fmaxf(fmaf(f3.y, scB.w, shB.w), 0.f);
        __half2 p0 = __floats2half2_rn(y0, y1);
        __half2 p1 = __floats2half2_rn(y2, y3);
        __half2 p2 = __floats2half2_rn(y4, y5);
        __half2 p3 = __floats2half2_rn(y6, y7);
        __half* dst = (__half*)g_s + (size_t)c * 128 + c8;
        asm volatile("red.global.add.noftz.v4.f16x2 [%0], {%1,%2,%3,%4};"
                     :: "l"(dst),
                        "r"(*reinterpret_cast<uint32_t*>(&p0)),
                        "r"(*reinterpret_cast<uint32_t*>(&p1)),
                        "r"(*reinterpret_cast<uint32_t*>(&p2)),
                        "r"(*reinterpret_cast<uint32_t*>(&p3))
                     : "memory");
        if ((lane & 15) == 0) atomicAdd(&g_cnt[c], 1);
    }
}

// ---------------- launch ------------------------------------------------------
extern "C" void kernel_launch(void* const* d_in, const int* in_sizes, int n_in,
                              void* d_out, int out_size)
{
    const float* x     = (const float*)d_in[0];
    const int*   eidx  = (const int*)  d_in[1];
    const float* eattr = (const float*)d_in[2];
    const float* W1  = (const float*)d_in[5];
    const float* b1  = (const float*)d_in[6];
    const float* g1  = (const float*)d_in[7];
    const float* be1 = (const float*)d_in[8];
    const float* W2  = (const float*)d_in[9];
    const float* b2  = (const float*)d_in[10];
    const float* g2  = (const float*)d_in[11];
    const float* be2 = (const float*)d_in[12];
    const float* Wl  = (const float*)d_in[13];
    const float* bl  = (const float*)d_in[14];
    float* out = (float*)d_out;

    const int* erow = eidx;
    const int* ecol = eidx + E_EDGES;

    cudaFuncSetAttribute(gemm1_mma, cudaFuncAttributeMaxDynamicSharedMemorySize, G3_TOT);
    cudaFuncSetAttribute(mma16_gemm<2, 0>, cudaFuncAttributeMaxDynamicSharedMemorySize, M_TOT);
    cudaFuncSetAttribute(mma16_gemm<4, 1>, cudaFuncAttributeMaxDynamicSharedMemorySize, M_TOT);
    cudaFuncSetAttribute(final_gemm, cudaFuncAttributeMaxDynamicSharedMemorySize, Q_TOT);

    const int MB = (N_NODES + 127) / 128;   // 391

    // 0) zero accumulators + prep weight images (+ final bias)
    zero_kernel<<<2048, 256>>>();
    prep_W<<<480, 256>>>(W1, W2, Wl, bl);

    // 1) P = x @ W1_top + b1 (fp16 single-pass)
    mma16_gemm<2, 0><<<dim3(MB, 1), 256, M_TOT>>>(x, N_NODES, b1);

    // 2) persistent fp16 1-pass: Y = eattr @ W1_bot + P[row]; fused BN1 stats
    gemm1_mma<<<G_GRID, 256, G3_TOT>>>(eattr, erow);

    // 3) BN1 scale/shift
    finalize_bn<<<1, 256>>>(g1, be1, 128, 1.f / (float)E_EDGES, 0);

    // 4) BN1 + ReLU + scatter (fp16 Y, fp16x2 vector atomics)
    scatter_kernel<<<2368, 256>>>(ecol);

    // 5) Z2 = concat(x, s/cnt) @ W2 + b2, fused h2in build + BN2 stats
    mma16_gemm<4, 1><<<dim3(MB, 2), 256, M_TOT>>>(x, N_NODES, b2);

    // 6) BN2 scale/shift
    finalize_bn<<<1, 256>>>(g2, be2, 256, 1.f / (float)N_NODES, 1);

    // 7) out = relu(relu(bn2(Z2)) @ Wl + bl)  (bf16 3-pass, Wl near-exact)
    final_gemm<<<dim3(MB, 1), 256, Q_TOT>>>(out, N_NODES);
}

// round 17
// speedup vs baseline: 1.8263x; 1.1822x over previous
#include <cuda_runtime.h>
#include <cuda_bf16.h>
#include <cuda_fp16.h>
#include <cstdint>

#define E_EDGES 1600000
#define N_NODES 50000
#define EPS_BN 1e-5f

// Physical-column permutation within each 64-col group:
//   storage position p holds logical column cOf(p) = 8*((p>>1)&7) + 2*(p>>4) + (p&1)
__host__ __device__ __forceinline__ int perm64(int p6) {
    return (((p6 >> 1) & 7) << 3) + ((p6 >> 4) << 1) + (p6 & 1);
}

// ---------------- scratch (device globals; no allocations allowed) ----------
__device__ __half g_Y[(size_t)E_EDGES * 128];     // permuted cols, fp16
__device__ float g_P[(size_t)N_NODES * 128];      // permuted cols
__device__ __half g_s[(size_t)N_NODES * 128];     // permuted cols, fp16
__device__ int   g_cnt[N_NODES];
__device__ float g_Z2[(size_t)N_NODES * 256];     // logical cols
__device__ float g_sum1[128], g_ssq1[128], g_scale1[128], g_shift1[128]; // physical
__device__ float g_sum2[256], g_ssq2[256], g_scale2[256], g_shift2[256];
__device__ float g_blv[128];                       // final-layer bias
__device__ float g_b1p[128];                       // b1 permuted
// Weight images (padded rows, uint4-clean)
__device__ uint4 g_W1bH16[1088];                   // W1_bot fp16 [64 k][136 n] (identity cols)
__device__ uint4 g_W1tH16[2176];                   // W1_top fp16 [128 k][136 n] (permuted cols)
__device__ uint4 g_W2H16[8448];                    // W2 fp16 [256 k][264 n] (rows 128+ permuted)
__device__ uint4 g_WlH[4352],  g_WlL[4352];        // Wl bf16 hi/lo [256 k][136 n]

__device__ __forceinline__ float4 ld4(const float* p) {
    return *reinterpret_cast<const float4*>(p);
}
__device__ __forceinline__ uint32_t smem_u32(const void* p) {
    uint32_t a;
    asm("{ .reg .u64 t; cvta.to.shared.u64 t, %1; cvt.u32.u64 %0, t; }" : "=r"(a) : "l"(p));
    return a;
}

// ---------------- warp MMA primitives (sm_80 baseline) ----------------------
__device__ __forceinline__ void mma_bf16(float* c, const uint32_t* a, const uint32_t* b) {
    asm volatile(
        "mma.sync.aligned.m16n8k16.row.col.f32.bf16.bf16.f32 "
        "{%0,%1,%2,%3}, {%4,%5,%6,%7}, {%8,%9}, {%0,%1,%2,%3};"
        : "+f"(c[0]), "+f"(c[1]), "+f"(c[2]), "+f"(c[3])
        : "r"(a[0]), "r"(a[1]), "r"(a[2]), "r"(a[3]), "r"(b[0]), "r"(b[1]));
}
__device__ __forceinline__ void mma_f16(float* c, const uint32_t* a, const uint32_t* b) {
    asm volatile(
        "mma.sync.aligned.m16n8k16.row.col.f32.f16.f16.f32 "
        "{%0,%1,%2,%3}, {%4,%5,%6,%7}, {%8,%9}, {%0,%1,%2,%3};"
        : "+f"(c[0]), "+f"(c[1]), "+f"(c[2]), "+f"(c[3])
        : "r"(a[0]), "r"(a[1]), "r"(a[2]), "r"(a[3]), "r"(b[0]), "r"(b[1]));
}
__device__ __forceinline__ void ldsm4(uint32_t* r, uint32_t addr) {
    asm volatile("ldmatrix.sync.aligned.m8n8.x4.shared.b16 {%0,%1,%2,%3}, [%4];"
        : "=r"(r[0]), "=r"(r[1]), "=r"(r[2]), "=r"(r[3]) : "r"(addr));
}
__device__ __forceinline__ void ldsm4t(uint32_t* r, uint32_t addr) {
    asm volatile("ldmatrix.sync.aligned.m8n8.x4.trans.shared.b16 {%0,%1,%2,%3}, [%4];"
        : "=r"(r[0]), "=r"(r[1]), "=r"(r[2]), "=r"(r[3]) : "r"(addr));
}
__device__ __forceinline__ void split_store(char* hi, char* lo, int j, float4 v) {
    __nv_bfloat16 h0 = __float2bfloat16_rn(v.x), h1 = __float2bfloat16_rn(v.y);
    __nv_bfloat16 h2 = __float2bfloat16_rn(v.z), h3 = __float2bfloat16_rn(v.w);
    __nv_bfloat162 hp0(h0, h1), hp1(h2, h3);
    __nv_bfloat162 lp0(__float2bfloat16_rn(v.x - __bfloat162float(h0)),
                       __float2bfloat16_rn(v.y - __bfloat162float(h1)));
    __nv_bfloat162 lp1(__float2bfloat16_rn(v.z - __bfloat162float(h2)),
                       __float2bfloat16_rn(v.w - __bfloat162float(h3)));
    *reinterpret_cast<uint2*>(hi + j * 8) =
        make_uint2(*reinterpret_cast<uint32_t*>(&hp0), *reinterpret_cast<uint32_t*>(&hp1));
    *reinterpret_cast<uint2*>(lo + j * 8) =
        make_uint2(*reinterpret_cast<uint32_t*>(&lp0), *reinterpret_cast<uint32_t*>(&lp1));
}
__device__ __forceinline__ void pack_f16_store(char* ai, int j, float4 v0, float4 v1) {
    __half2 a = __floats2half2_rn(v0.x, v0.y);
    __half2 b = __floats2half2_rn(v0.z, v0.w);
    __half2 c = __floats2half2_rn(v1.x, v1.y);
    __half2 d = __floats2half2_rn(v1.z, v1.w);
    *reinterpret_cast<uint4*>(ai + j * 8) =
        make_uint4(*reinterpret_cast<uint32_t*>(&a), *reinterpret_cast<uint32_t*>(&b),
                   *reinterpret_cast<uint32_t*>(&c), *reinterpret_cast<uint32_t*>(&d));
}
__device__ __forceinline__ void cp_async16(uint32_t saddr, const void* gptr) {
    asm volatile("cp.async.cg.shared.global [%0], [%1], 16;"
                 :: "r"(saddr), "l"(gptr) : "memory");
}
__device__ __forceinline__ void prefetchL1(const void* gptr) {
    asm volatile("prefetch.global.L1 [%0];" :: "l"(gptr));
}
__device__ __forceinline__ uint32_t h2bits(__half2 h) {
    return *reinterpret_cast<uint32_t*>(&h);
}

// ---------------- zero scratch ----------------------------------------------
__global__ void zero_kernel() {
    int idx = blockIdx.x * blockDim.x + threadIdx.x;
    int stride = gridDim.x * blockDim.x;
    uint4 z4 = make_uint4(0u, 0u, 0u, 0u);
    const int total4 = N_NODES * 16;
    uint4* s4 = reinterpret_cast<uint4*>(g_s);
    for (int i = idx; i < total4; i += stride) s4[i] = z4;
    for (int i = idx; i < N_NODES; i += stride) g_cnt[i] = 0;
    if (idx < 128) { g_sum1[idx] = 0.f; g_ssq1[idx] = 0.f; }
    if (idx < 256) { g_sum2[idx] = 0.f; g_ssq2[idx] = 0.f; }
}

// ---------------- prep: weight images (+ permutations) ------------------------
__global__ void prep_W(const float* __restrict__ W1, const float* __restrict__ W2,
                       const float* __restrict__ Wl, const float* __restrict__ bl,
                       const float* __restrict__ b1) {
    int idx = blockIdx.x * blockDim.x + threadIdx.x;
    if (idx < 8192) {                       // W1_bot fp16 (identity cols)
        int k = idx >> 7, n = idx & 127;
        __half h = __float2half_rn(W1[(size_t)(128 + k) * 128 + n]);
        reinterpret_cast<uint16_t*>(g_W1bH16)[k * 136 + n] = *reinterpret_cast<uint16_t*>(&h);
        if (idx < 128) {
            g_blv[idx] = bl[idx];
            int L = (idx >> 6) * 64 + perm64(idx & 63);
            g_b1p[idx] = b1[L];
        }
    } else if (idx < 24576) {               // W1_top fp16, PERMUTED cols
        int l = idx - 8192, k = l >> 7, n = l & 127;
        int L = (n >> 6) * 64 + perm64(n & 63);
        __half h = __float2half_rn(W1[(size_t)k * 128 + L]);
        reinterpret_cast<uint16_t*>(g_W1tH16)[k * 136 + n] = *reinterpret_cast<uint16_t*>(&h);
    } else if (idx < 90112) {               // W2 fp16; rows 128+ PERMUTED
        int l = idx - 24576, k = l >> 8, n = l & 255;
        int srcRow = k;
        if (k >= 128) {
            int p = k - 128;
            srcRow = 128 + (p >> 6) * 64 + perm64(p & 63);
        }
        __half h = __float2half_rn(W2[(size_t)srcRow * 256 + n]);
        reinterpret_cast<uint16_t*>(g_W2H16)[k * 264 + n] = *reinterpret_cast<uint16_t*>(&h);
    } else if (idx < 122880) {              // Wl bf16 hi/lo (identity)
        int l = idx - 90112, k = l >> 7, n = l & 127;
        float f = Wl[(size_t)k * 128 + n];
        __nv_bfloat16 h = __float2bfloat16_rn(f);
        __nv_bfloat16 lo = __float2bfloat16_rn(f - __bfloat162float(h));
        reinterpret_cast<uint16_t*>(g_WlH)[k * 136 + n] = *reinterpret_cast<uint16_t*>(&h);
        reinterpret_cast<uint16_t*>(g_WlL)[k * 136 + n] = *reinterpret_cast<uint16_t*>(&lo);
    }
}

// ---------------- SMEM layouts ------------------------------------------------
#define A_STRIDE 144
#define Q_AHI 0
#define Q_ALO 18432
#define Q_WHI 36864
#define Q_WLO 54272
#define Q_TOT 73216
#define M_A 0
#define M_W 18432
#define M_BIAS 35840
#define M_SUM 36352
#define M_SSQ 36864
#define M_TOT 37376
#define G3_A 0
#define G3_W 18432
#define G3_STAGE 35840
#define G3_SROWSTG 70656
#define G3_SROW 71168
#define G3_SUM 71680
#define G3_SSQ 72192
#define G3_TOT 72704
#define G_GRID 296
#define G_NT (E_EDGES / 128)

// ---------------- gemm1 (persistent): Y[perm] = eattr@W1_bot + P[row][perm] --
__global__ void __launch_bounds__(256, 2)
gemm1_mma(const float* __restrict__ eattr, const int* __restrict__ erow) {
    extern __shared__ char smem[];
    const uint32_t sb = smem_u32(smem);
    const int tid = threadIdx.x, wid = tid >> 5, lane = tid & 31;

    {
        uint4* dw = reinterpret_cast<uint4*>(smem + G3_W);
        for (int i = tid; i < 1088; i += 256) dw[i] = g_W1bH16[i];
    }
    if (tid < 128) {
        ((float*)(smem + G3_SUM))[tid] = 0.f;
        ((float*)(smem + G3_SSQ))[tid] = 0.f;
    }

    {
        int t0 = blockIdx.x;
        const char* src = (const char*)(eattr + (size_t)t0 * 128 * 64);
        #pragma unroll
        for (int i = tid; i < 2048; i += 256) {
            int r = i >> 4, q = i & 15;
            cp_async16(sb + G3_STAGE + r * 272 + q * 16, src + (size_t)r * 256 + q * 16);
        }
        if (tid < 32)
            cp_async16(sb + G3_SROWSTG + tid * 16,
                       (const char*)(erow + (size_t)t0 * 128) + tid * 16);
        asm volatile("cp.async.commit_group;" ::: "memory");
    }

    const int m0 = (wid & 3) * 32;
    const int n0 = (wid >> 2) * 64;
    const uint32_t aRowOff = (uint32_t)(m0 + (lane & 15)) * (uint32_t)A_STRIDE
                           + (uint32_t)(lane >> 4) * 16u;
    const uint32_t bOff = (uint32_t)((lane & 7) + ((lane >> 3) & 1) * 8) * 272u
                        + ((uint32_t)(lane >> 4) * 8u + (uint32_t)n0) * 2u;
    const int g = lane >> 2, q = lane & 3;
    const int colBase = n0 + q * 16;   // physical col base (16 consecutive)
    const int* s_row = (const int*)(smem + G3_SROW);
    float* s_sum = (float*)(smem + G3_SUM);
    float* s_ssq = (float*)(smem + G3_SSQ);

    float csum[8][2], cssq[8][2];
    #pragma unroll
    for (int ni = 0; ni < 8; ++ni) {
        csum[ni][0] = 0.f; csum[ni][1] = 0.f;
        cssq[ni][0] = 0.f; cssq[ni][1] = 0.f;
    }

    for (int t = blockIdx.x; t < G_NT; t += G_GRID) {
        asm volatile("cp.async.wait_group 0;" ::: "memory");
        __syncthreads();

        {
            const int r = tid >> 1, h = tid & 1;
            const char* srow = smem + G3_STAGE + r * 272;
            char* ai = smem + G3_A + r * A_STRIDE;
            #pragma unroll
            for (int p = 0; p < 4; ++p) {
                int j = h * 8 + p * 2;
                float4 v0 = *reinterpret_cast<const float4*>(srow + j * 16);
                float4 v1 = *reinterpret_cast<const float4*>(srow + j * 16 + 16);
                pack_f16_store(ai, j, v0, v1);
            }
            if (tid < 128)
                ((int*)(smem + G3_SROW))[tid] = ((const int*)(smem + G3_SROWSTG))[tid];
        }
        __syncthreads();

        int G00 = s_row[m0 + g],      G01 = s_row[m0 + g + 8];
        int G10 = s_row[m0 + 16 + g], G11 = s_row[m0 + 16 + g + 8];
        {
            const float* pb = g_P;
            prefetchL1(pb + (size_t)G00 * 128 + colBase);
            prefetchL1(pb + (size_t)G01 * 128 + colBase);
            prefetchL1(pb + (size_t)G10 * 128 + colBase);
            prefetchL1(pb + (size_t)G11 * 128 + colBase);
        }

        if (t + G_GRID < G_NT) {
            int tn = t + G_GRID;
            const char* src = (const char*)(eattr + (size_t)tn * 128 * 64);
            #pragma unroll
            for (int i = tid; i < 2048; i += 256) {
                int r = i >> 4, qq = i & 15;
                cp_async16(sb + G3_STAGE + r * 272 + qq * 16, src + (size_t)r * 256 + qq * 16);
            }
            if (tid < 32)
                cp_async16(sb + G3_SROWSTG + tid * 16,
                           (const char*)(erow + (size_t)tn * 128) + tid * 16);
        }
        asm volatile("cp.async.commit_group;" ::: "memory");

        float acc[2][8][4];
        #pragma unroll
        for (int mi = 0; mi < 2; ++mi)
            #pragma unroll
            for (int ni = 0; ni < 8; ++ni)
                #pragma unroll
                for (int c = 0; c < 4; ++c) acc[mi][ni][c] = 0.f;

        #pragma unroll
        for (int kt = 0; kt < 4; ++kt) {
            const uint32_t k0b = (uint32_t)kt * 32u;
            const uint32_t kwb = (uint32_t)kt * 4352u;
            uint32_t a0[4], a1[4];
            ldsm4(a0, sb + G3_A + aRowOff + k0b);
            ldsm4(a1, sb + G3_A + aRowOff + 16u * A_STRIDE + k0b);

            #pragma unroll
            for (int ni2 = 0; ni2 < 4; ++ni2) {
                uint32_t th[4];
                ldsm4t(th, sb + G3_W + bOff + kwb + (uint32_t)ni2 * 32u);
                mma_f16(acc[0][2 * ni2],     a0, th);
                mma_f16(acc[0][2 * ni2 + 1], a0, th + 2);
                mma_f16(acc[1][2 * ni2],     a1, th);
                mma_f16(acc[1][2 * ni2 + 1], a1, th + 2);
            }
        }

        // ---- epilogue: permuted contiguous storage, vectorized ----
        const int mBase = t * 128;
        #pragma unroll
        for (int mi = 0; mi < 2; ++mi) {
            const int r0 = mBase + m0 + mi * 16 + g;
            const int Ga = (mi == 0) ? G00 : G10;
            const int Gb = (mi == 0) ? G01 : G11;
            float P0[16], P1[16];
            #pragma unroll
            for (int u = 0; u < 4; ++u) {
                *reinterpret_cast<float4*>(P0 + 4 * u) =
                    ld4(g_P + (size_t)Ga * 128 + colBase + 4 * u);
                *reinterpret_cast<float4*>(P1 + 4 * u) =
                    ld4(g_P + (size_t)Gb * 128 + colBase + 4 * u);
            }
            uint32_t ua[8], ub[8];
            #pragma unroll
            for (int ni = 0; ni < 8; ++ni) {
                float y0 = acc[mi][ni][0] + P0[2 * ni];
                float y1 = acc[mi][ni][1] + P0[2 * ni + 1];
                float y2 = acc[mi][ni][2] + P1[2 * ni];
                float y3 = acc[mi][ni][3] + P1[2 * ni + 1];
                ua[ni] = h2bits(__floats2half2_rn(y0, y1));
                ub[ni] = h2bits(__floats2half2_rn(y2, y3));
                csum[ni][0] += y0 + y2;
                csum[ni][1] += y1 + y3;
                cssq[ni][0] += y0 * y0 + y2 * y2;
                cssq[ni][1] += y1 * y1 + y3 * y3;
            }
            uint4* dst0 = reinterpret_cast<uint4*>(g_Y + (size_t)r0 * 128 + colBase);
            uint4* dst1 = reinterpret_cast<uint4*>(g_Y + (size_t)(r0 + 8) * 128 + colBase);
            __stcs(dst0,     make_uint4(ua[0], ua[1], ua[2], ua[3]));
            __stcs(dst0 + 1, make_uint4(ua[4], ua[5], ua[6], ua[7]));
            __stcs(dst1,     make_uint4(ub[0], ub[1], ub[2], ub[3]));
            __stcs(dst1 + 1, make_uint4(ub[4], ub[5], ub[6], ub[7]));
        }
    }

    // ---- BN1 stats flush (physical indices) ----
    #pragma unroll
    for (int ni = 0; ni < 8; ++ni)
        #pragma unroll
        for (int par = 0; par < 2; ++par) {
            float s = csum[ni][par], qv = cssq[ni][par];
            #pragma unroll
            for (int o = 4; o < 32; o <<= 1) {
                s += __shfl_xor_sync(0xFFFFFFFFu, s, o);
                qv += __shfl_xor_sync(0xFFFFFFFFu, qv, o);
            }
            if (g == 0) {
                atomicAdd(&s_sum[colBase + 2 * ni + par], s);
                atomicAdd(&s_ssq[colBase + 2 * ni + par], qv);
            }
        }
    __syncthreads();
    if (tid < 128) {
        atomicAdd(&g_sum1[tid], s_sum[tid]);
        atomicAdd(&g_ssq1[tid], s_ssq[tid]);
    }
}

// ---------------- fp16 single-pass node GEMM ---------------------------------
// ASEL 0: A = x [M,128] (KCH=2), out = g_P (perm cols via permuted W image/bias)
// ASEL 1: A = concat(x, g_s/cnt) [M,256] (KCH=4), out = g_Z2 (+BN2 stats)
template<int KCH, int ASEL>
__global__ void __launch_bounds__(256, 2)
mma16_gemm(const float* __restrict__ x, int M, const float* __restrict__ bias)
{
    extern __shared__ char smem[];
    const uint32_t sb = smem_u32(smem);
    const int tid = threadIdx.x, wid = tid >> 5, lane = tid & 31;
    const int mBase = blockIdx.x * 128;
    const int nBase = blockIdx.y * 128;

    const uint4* WH = (ASEL == 0) ? g_W1tH16 : g_W2H16;
    const int WR16 = (ASEL == 0) ? 17 : 33;
    float* outp = (ASEL == 0) ? (float*)g_P : (float*)g_Z2;
    const int outLd = (ASEL == 0) ? 128 : 256;

    if (tid < 128) {
        ((float*)(smem + M_BIAS))[tid] = (ASEL == 0) ? g_b1p[nBase + tid]
                                                     : bias[nBase + tid];
        ((float*)(smem + M_SUM))[tid] = 0.f;
        ((float*)(smem + M_SSQ))[tid] = 0.f;
    }

    const int m0 = (wid & 3) * 32;
    const int n0 = (wid >> 2) * 64;
    float acc[2][8][4];
    #pragma unroll
    for (int mi = 0; mi < 2; ++mi)
        #pragma unroll
        for (int ni = 0; ni < 8; ++ni)
            #pragma unroll
            for (int c = 0; c < 4; ++c) acc[mi][ni][c] = 0.f;

    const uint32_t aRowOff = (uint32_t)(m0 + (lane & 15)) * (uint32_t)A_STRIDE
                           + (uint32_t)(lane >> 4) * 16u;
    const uint32_t bOff = (uint32_t)((lane & 7) + ((lane >> 3) & 1) * 8) * 272u
                        + ((uint32_t)(lane >> 4) * 8u + (uint32_t)n0) * 2u;

    #pragma unroll 1
    for (int c = 0; c < KCH; ++c) {
        if (c) __syncthreads();
        {
            uint4* dw = reinterpret_cast<uint4*>(smem + M_W);
            const uint4* sh = WH + (size_t)(c * 64) * WR16 + (nBase >> 3);
            for (int i = tid; i < 1088; i += 256) {
                int kk = i / 17, qq = i - kk * 17;
                dw[i] = sh[(size_t)kk * WR16 + qq];
            }
        }
        {
            const int r = tid >> 1, h = tid & 1, rg = mBase + r;
            char* ai = smem + M_A + r * A_STRIDE;
            if (ASEL == 1 && c >= 2) {
                float invc = 0.f;
                const __half* hbase = (const __half*)g_s + (size_t)rg * 128 + (c - 2) * 64;
                if (rg < M) {
                    int ct = g_cnt[rg];
                    invc = (ct > 0) ? (1.f / (float)ct) : 0.f;
                }
                #pragma unroll
                for (int p = 0; p < 4; ++p) {
                    int j = h * 8 + p * 2;
                    float4 v0 = make_float4(0.f, 0.f, 0.f, 0.f);
                    float4 v1 = make_float4(0.f, 0.f, 0.f, 0.f);
                    if (rg < M) {
                        uint2 ra = *reinterpret_cast<const uint2*>(hbase + j * 4);
                        uint2 rb = *reinterpret_cast<const uint2*>(hbase + j * 4 + 4);
                        float2 f0 = __half22float2(*reinterpret_cast<__half2*>(&ra.x));
                        float2 f1 = __half22float2(*reinterpret_cast<__half2*>(&ra.y));
                        float2 f2 = __half22float2(*reinterpret_cast<__half2*>(&rb.x));
                        float2 f3 = __half22float2(*reinterpret_cast<__half2*>(&rb.y));
                        v0 = make_float4(f0.x * invc, f0.y * invc, f1.x * invc, f1.y * invc);
                        v1 = make_float4(f2.x * invc, f2.y * invc, f3.x * invc, f3.y * invc);
                    }
                    pack_f16_store(ai, j, v0, v1);
                }
            } else {
                const float* base = x + (size_t)rg * 128 + c * 64;
                #pragma unroll
                for (int p = 0; p < 4; ++p) {
                    int j = h * 8 + p * 2;
                    float4 v0 = make_float4(0.f, 0.f, 0.f, 0.f);
                    float4 v1 = make_float4(0.f, 0.f, 0.f, 0.f);
                    if (rg < M) {
                        v0 = ld4(base + j * 4);
                        v1 = ld4(base + j * 4 + 4);
                    }
                    pack_f16_store(ai, j, v0, v1);
                }
            }
        }
        __syncthreads();

        #pragma unroll
        for (int kt = 0; kt < 4; ++kt) {
            const uint32_t k0b = (uint32_t)kt * 32u;
            const uint32_t kwb = (uint32_t)kt * 4352u;
            uint32_t a0[4], a1[4];
            ldsm4(a0, sb + M_A + aRowOff + k0b);
            ldsm4(a1, sb + M_A + aRowOff + 16u * A_STRIDE + k0b);
            #pragma unroll
            for (int ni2 = 0; ni2 < 4; ++ni2) {
                uint32_t th[4];
                ldsm4t(th, sb + M_W + bOff + kwb + (uint32_t)ni2 * 32u);
                mma_f16(acc[0][2 * ni2],     a0, th);
                mma_f16(acc[0][2 * ni2 + 1], a0, th + 2);
                mma_f16(acc[1][2 * ni2],     a1, th);
                mma_f16(acc[1][2 * ni2 + 1], a1, th + 2);
            }
        }
    }
    __syncthreads();

    const float* bs = (const float*)(smem + M_BIAS);
    float* s_sum = (float*)(smem + M_SUM);
    float* s_ssq = (float*)(smem + M_SSQ);
    const int g = lane >> 2, t2 = (lane & 3) * 2;

    float csum[8][2], cssq[8][2];
    if (ASEL == 1) {
        #pragma unroll
        for (int ni = 0; ni < 8; ++ni) {
            csum[ni][0] = 0.f; csum[ni][1] = 0.f;
            cssq[ni][0] = 0.f; cssq[ni][1] = 0.f;
        }
    }

    #pragma unroll
    for (int mi = 0; mi < 2; ++mi) {
        const int row = mBase + m0 + mi * 16 + g;
        const bool v0 = row < M, v1 = (row + 8) < M;
        #pragma unroll
        for (int ni = 0; ni < 8; ++ni) {
            const int col = n0 + ni * 8 + t2;
            float b0 = bs[col], b1 = bs[col + 1];
            float y0 = acc[mi][ni][0] + b0;
            float y1 = acc[mi][ni][1] + b1;
            float y2 = acc[mi][ni][2] + b0;
            float y3 = acc[mi][ni][3] + b1;
            if (v0)
                *reinterpret_cast<float2*>(outp + (size_t)row * outLd + nBase + col)
                    = make_float2(y0, y1);
            if (v1)
                *reinterpret_cast<float2*>(outp + (size_t)(row + 8) * outLd + nBase + col)
                    = make_float2(y2, y3);
            if (ASEL == 1) {
                if (v0) {
                    csum[ni][0] += y0; csum[ni][1] += y1;
                    cssq[ni][0] += y0 * y0; cssq[ni][1] += y1 * y1;
                }
                if (v1) {
                    csum[ni][0] += y2; csum[ni][1] += y3;
                    cssq[ni][0] += y2 * y2; cssq[ni][1] += y3 * y3;
                }
            }
        }
    }
    if (ASEL == 1) {
        #pragma unroll
        for (int ni = 0; ni < 8; ++ni)
            #pragma unroll
            for (int par = 0; par < 2; ++par) {
                float s = csum[ni][par], qv = cssq[ni][par];
                #pragma unroll
                for (int o = 4; o < 32; o <<= 1) {
                    s += __shfl_xor_sync(0xFFFFFFFFu, s, o);
                    qv += __shfl_xor_sync(0xFFFFFFFFu, qv, o);
                }
                if (g == 0) {
                    atomicAdd(&s_sum[n0 + ni * 8 + t2 + par], s);
                    atomicAdd(&s_ssq[n0 + ni * 8 + t2 + par], qv);
                }
            }
        __syncthreads();
        if (tid < 128) {
            atomicAdd(&g_sum2[nBase + tid], s_sum[tid]);
            atomicAdd(&g_ssq2[nBase + tid], s_ssq[tid]);
        }
    }
}

// ---------------- final GEMM (bf16 3-pass): out = relu(relu(bn2(Z2))@Wl+bl) --
__global__ void __launch_bounds__(256, 2)
final_gemm(float* __restrict__ outExt, int M)
{
    extern __shared__ char smem[];
    const uint32_t sb = smem_u32(smem);
    const int tid = threadIdx.x, wid = tid >> 5, lane = tid & 31;
    const int mBase = blockIdx.x * 128;

    const int m0 = (wid & 3) * 32;
    const int n0 = (wid >> 2) * 64;
    float acc[2][8][4];
    #pragma unroll
    for (int mi = 0; mi < 2; ++mi)
        #pragma unroll
        for (int ni = 0; ni < 8; ++ni)
            #pragma unroll
            for (int c = 0; c < 4; ++c) acc[mi][ni][c] = 0.f;

    const uint32_t aRowOff = (uint32_t)(m0 + (lane & 15)) * (uint32_t)A_STRIDE
                           + (uint32_t)(lane >> 4) * 16u;
    const uint32_t bOff = (uint32_t)((lane & 7) + ((lane >> 3) & 1) * 8) * 272u
                        + ((uint32_t)(lane >> 4) * 8u + (uint32_t)n0) * 2u;

    #pragma unroll 1
    for (int c = 0; c < 4; ++c) {
        if (c) __syncthreads();
        {
            uint4* dh = reinterpret_cast<uint4*>(smem + Q_WHI);
            uint4* dl = reinterpret_cast<uint4*>(smem + Q_WLO);
            const uint4* sh = g_WlH + (size_t)(c * 64) * 17;
            const uint4* sl = g_WlL + (size_t)(c * 64) * 17;
            for (int i = tid; i < 1088; i += 256) {
                int kk = i / 17, qq = i - kk * 17;
                dh[i] = sh[(size_t)kk * 17 + qq];
                dl[i] = sl[(size_t)kk * 17 + qq];
            }
        }
        {
            const int r = tid >> 1, h = tid & 1, rg = mBase + r;
            char* ahi = smem + Q_AHI + r * A_STRIDE;
            char* alo = smem + Q_ALO + r * A_STRIDE;
            const float4* ar = reinterpret_cast<const float4*>(
                (const float*)g_Z2 + (size_t)rg * 256 + c * 64);
            #pragma unroll
            for (int jj = 0; jj < 8; ++jj) {
                int j = h * 8 + jj;
                float4 v = make_float4(0.f, 0.f, 0.f, 0.f);
                if (rg < M) {
                    v = ar[j];
                    int kg = c * 64 + j * 4;
                    float4 sc = ld4(g_scale2 + kg), sh4 = ld4(g_shift2 + kg);
                    v.x = fmaxf(fmaf(v.x, sc.x, sh4.x), 0.f);
                    v.y = fmaxf(fmaf(v.y, sc.y, sh4.y), 0.f);
                    v.z = fmaxf(fmaf(v.z, sc.z, sh4.z), 0.f);
                    v.w = fmaxf(fmaf(v.w, sc.w, sh4.w), 0.f);
                }
                split_store(ahi, alo, j, v);
            }
        }
        __syncthreads();

        #pragma unroll
        for (int kt = 0; kt < 4; ++kt) {
            const uint32_t k0b = (uint32_t)kt * 32u;
            const uint32_t kwb = (uint32_t)kt * 4352u;
            uint32_t ah[2][4], al[2][4];
            ldsm4(ah[0], sb + Q_AHI + aRowOff + k0b);
            ldsm4(ah[1], sb + Q_AHI + aRowOff + 16u * A_STRIDE + k0b);
            ldsm4(al[0], sb + Q_ALO + aRowOff + k0b);
            ldsm4(al[1], sb + Q_ALO + aRowOff + 16u * A_STRIDE + k0b);

            #pragma unroll
            for (int ni2 = 0; ni2 < 4; ++ni2) {
                uint32_t th[4], tl[4];
                ldsm4t(th, sb + Q_WHI + bOff + kwb + (uint32_t)ni2 * 32u);
                ldsm4t(tl, sb + Q_WLO + bOff + kwb + (uint32_t)ni2 * 32u);
                #pragma unroll
                for (int mi = 0; mi < 2; ++mi) {
                    mma_bf16(acc[mi][2 * ni2],     ah[mi], th);
                    mma_bf16(acc[mi][2 * ni2],     al[mi], th);
                    mma_bf16(acc[mi][2 * ni2],     ah[mi], tl);
                    mma_bf16(acc[mi][2 * ni2 + 1], ah[mi], th + 2);
                    mma_bf16(acc[mi][2 * ni2 + 1], al[mi], th + 2);
                    mma_bf16(acc[mi][2 * ni2 + 1], ah[mi], tl + 2);
                }
            }
        }
    }
    __syncthreads();

    const int g = lane >> 2, t2 = (lane & 3) * 2;
    #pragma unroll
    for (int mi = 0; mi < 2; ++mi) {
        const int row = mBase + m0 + mi * 16 + g;
        const bool v0 = row < M, v1 = (row + 8) < M;
        #pragma unroll
        for (int ni = 0; ni < 8; ++ni) {
            const int col = n0 + ni * 8 + t2;
            float bb0 = g_blv[col], bb1 = g_blv[col + 1];
            float y0 = fmaxf(acc[mi][ni][0] + bb0, 0.f);
            float y1 = fmaxf(acc[mi][ni][1] + bb1, 0.f);
            float y2 = fmaxf(acc[mi][ni][2] + bb0, 0.f);
            float y3 = fmaxf(acc[mi][ni][3] + bb1, 0.f);
            if (v0)
                *reinterpret_cast<float2*>(outExt + (size_t)row * 128 + col)
                    = make_float2(y0, y1);
            if (v1)
                *reinterpret_cast<float2*>(outExt + (size_t)(row + 8) * 128 + col)
                    = make_float2(y2, y3);
        }
    }
}

// ---------------- BN finalize (which==0 maps physical->logical gamma/beta) ----
__global__ void finalize_bn(const float* __restrict__ gamma,
                            const float* __restrict__ beta,
                            int C, float invM, int which)
{
    int i = blockIdx.x * blockDim.x + threadIdx.x;
    if (i < C) {
        const float* sum = (which == 0) ? g_sum1 : g_sum2;
        const float* ssq = (which == 0) ? g_ssq1 : g_ssq2;
        float*     scale = (which == 0) ? g_scale1 : g_scale2;
        float*     shift = (which == 0) ? g_shift1 : g_shift2;
        int L = i;
        if (which == 0) L = (i >> 6) * 64 + perm64(i & 63);
        float mu  = sum[i] * invM;
        float var = ssq[i] * invM - mu * mu;
        float inv = rsqrtf(var + EPS_BN);
        float sc  = gamma[L] * inv;
        scale[i] = sc;
        shift[i] = beta[L] - mu * sc;
    }
}

// ---------------- BN+ReLU then scatter-add (all physical, unchanged) ---------
__global__ void scatter_kernel(const int* __restrict__ ecol) {
    const int lane   = threadIdx.x & 31;
    const int warp   = (blockIdx.x * blockDim.x + threadIdx.x) >> 5;
    const int nWarps = (gridDim.x * blockDim.x) >> 5;
    const int sub    = lane >> 4;
    const int c8     = (lane & 15) << 3;

    float4 scA = *reinterpret_cast<const float4*>(&g_scale1[c8]);
    float4 scB = *reinterpret_cast<const float4*>(&g_scale1[c8 + 4]);
    float4 shA = *reinterpret_cast<const float4*>(&g_shift1[c8]);
    float4 shB = *reinterpret_cast<const float4*>(&g_shift1[c8 + 4]);

    for (int e2 = warp * 2; e2 < E_EDGES; e2 += nWarps * 2) {
        int e = e2 + sub;
        int c = ecol[e];
        uint4 raw = __ldcs(reinterpret_cast<const uint4*>(&g_Y[(size_t)e * 128 + c8]));
        float2 f0 = __half22float2(*reinterpret_cast<__half2*>(&raw.x));
        float2 f1 = __half22float2(*reinterpret_cast<__half2*>(&raw.y));
        float2 f2 = __half22float2(*reinterpret_cast<__half2*>(&raw.z));
        float2 f3 = __half22float2(*reinterpret_cast<__half2*>(&raw.w));
        float y0 = fmaxf(fmaf(f0.x, scA.x, shA.x), 0.f);
        float y1 = fmaxf(fmaf(f0.y, scA.y, shA.y), 0.f);
        float y2 = fmaxf(fmaf(f1.x, scA.z, shA.z), 0.f);
        float y3 = fmaxf(fmaf(f1.y, scA.w, shA.w), 0.f);
        float y4 = fmaxf(fmaf(f2.x, scB.x, shB.x), 0.f);
        float y5 = fmaxf(fmaf(f2.y, scB.y, shB.y), 0.f);
        float y6 = fmaxf(fmaf(f3.x, scB.z, shB.z), 0.f);
        float y7 = fmaxf(fmaf(f3.y, scB.w, shB.w), 0.f);
        __half2 p0 = __floats2half2_rn(y0, y1);
        __half2 p1 = __floats2half2_rn(y2, y3);
        __half2 p2 = __floats2half2_rn(y4, y5);
        __half2 p3 = __floats2half2_rn(y6, y7);
        __half* dst = (__half*)g_s + (size_t)c * 128 + c8;
        asm volatile("red.global.add.noftz.v4.f16x2 [%0], {%1,%2,%3,%4};"
                     :: "l"(dst),
                        "r"(*reinterpret_cast<uint32_t*>(&p0)),
                        "r"(*reinterpret_cast<uint32_t*>(&p1)),
                        "r"(*reinterpret_cast<uint32_t*>(&p2)),
                        "r"(*reinterpret_cast<uint32_t*>(&p3))
                     : "memory");
        if ((lane & 15) == 0) atomicAdd(&g_cnt[c], 1);
    }
}

// ---------------- launch ------------------------------------------------------
extern "C" void kernel_launch(void* const* d_in, const int* in_sizes, int n_in,
                              void* d_out, int out_size)
{
    const float* x     = (const float*)d_in[0];
    const int*   eidx  = (const int*)  d_in[1];
    const float* eattr = (const float*)d_in[2];
    const float* W1  = (const float*)d_in[5];
    const float* b1  = (const float*)d_in[6];
    const float* g1  = (const float*)d_in[7];
    const float* be1 = (const float*)d_in[8];
    const float* W2  = (const float*)d_in[9];
    const float* b2  = (const float*)d_in[10];
    const float* g2  = (const float*)d_in[11];
    const float* be2 = (const float*)d_in[12];
    const float* Wl  = (const float*)d_in[13];
    const float* bl  = (const float*)d_in[14];
    float* out = (float*)d_out;

    const int* erow = eidx;
    const int* ecol = eidx + E_EDGES;

    cudaFuncSetAttribute(gemm1_mma, cudaFuncAttributeMaxDynamicSharedMemorySize, G3_TOT);
    cudaFuncSetAttribute(mma16_gemm<2, 0>, cudaFuncAttributeMaxDynamicSharedMemorySize, M_TOT);
    cudaFuncSetAttribute(mma16_gemm<4, 1>, cudaFuncAttributeMaxDynamicSharedMemorySize, M_TOT);
    cudaFuncSetAttribute(final_gemm, cudaFuncAttributeMaxDynamicSharedMemorySize, Q_TOT);

    const int MB = (N_NODES + 127) / 128;   // 391

    // 0) zero accumulators + prep weight images (with permutations)
    zero_kernel<<<2048, 256>>>();
    prep_W<<<480, 256>>>(W1, W2, Wl, bl, b1);

    // 1) P[perm] = x @ W1_top[perm] + b1[perm]
    mma16_gemm<2, 0><<<dim3(MB, 1), 256, M_TOT>>>(x, N_NODES, b1);

    // 2) persistent: Y[perm] = eattr @ W1_bot + P[row][perm]; BN1 stats (phys)
    gemm1_mma<<<G_GRID, 256, G3_TOT>>>(eattr, erow);

    // 3) BN1 scale/shift (physical, gamma/beta remapped)
    finalize_bn<<<1, 256>>>(g1, be1, 128, 1.f / (float)E_EDGES, 0);

    // 4) BN1 + ReLU + scatter (physical throughout)
    scatter_kernel<<<2368, 256>>>(ecol);

    // 5) Z2 = concat(x, s/cnt) @ W2' + b2 (W2 rows permuted to match g_s)
    mma16_gemm<4, 1><<<dim3(MB, 2), 256, M_TOT>>>(x, N_NODES, b2);

    // 6) BN2 scale/shift
    finalize_bn<<<1, 256>>>(g2, be2, 256, 1.f / (float)N_NODES, 1);

    // 7) out = relu(relu(bn2(Z2)) @ Wl + bl)
    final_gemm<<<dim3(MB, 1), 256, Q_TOT>>>(out, N_NODES);
}